// round 5
// baseline (speedup 1.0000x reference)
#include <cuda_runtime.h>

typedef unsigned long long ull;

// ---------------- packed f32x2 PTX helpers ----------------
__device__ __forceinline__ ull pack2(float lo, float hi) {
    ull r; asm("mov.b64 %0, {%1, %2};" : "=l"(r) : "f"(lo), "f"(hi)); return r;
}
__device__ __forceinline__ void unpack2(ull v, float& lo, float& hi) {
    asm("mov.b64 {%0, %1}, %2;" : "=f"(lo), "=f"(hi) : "l"(v));
}
__device__ __forceinline__ void fma2(ull& d, ull a, ull b) {
    asm("fma.rn.f32x2 %0, %1, %2, %0;" : "+l"(d) : "l"(a), "l"(b));
}
__device__ __forceinline__ ull mul2(ull a, ull b) {
    ull d; asm("mul.rn.f32x2 %0, %1, %2;" : "=l"(d) : "l"(a), "l"(b)); return d;
}
__device__ __forceinline__ void add2(ull& d, ull a) {
    asm("add.rn.f32x2 %0, %0, %1;" : "+l"(d) : "l"(a));
}

// ---------------- problem constants ----------------
#define Bn   16
#define Nn   2048
#define DIN  512
#define DK   10
#define NH   2
#define DH   5
#define HID  20
#define DOUT 512
#define BH   (Bn * NH)          // 32
#define ROWS (Bn * Nn)          // 32768

// ---------------- device scratch ----------------
__device__ float g_Q[BH][Nn][8];       // Q pre-scaled by 1/sqrt(5)
__device__ float g_K[BH][Nn][8];
__device__ float g_V[BH][Nn][8];
// attention partials per key-quarter: [bh][q][kq][ a0..a4, den, pad, pad ]
__device__ float g_A[BH][Nn][4][8];

// =====================================================================
// Kernel 1: fused QKV projection.
// Grid 512, 256 threads = 32 row-PAIRS x 8 k-slices. Each thread computes
// 2 rows x 30 cols so the 8 W-LDS per k are amortized over 60 MACs.
// x and W staged in smem per 64-k chunk (coalesced gmem reads).
// 8-way k partials combined through smem; kq==0 does the epilogue.
// =====================================================================
#define PRJ_ROWS 64
#define XPAD 65

__global__ __launch_bounds__(256, 3) void proj_kernel(
    const float* __restrict__ x,
    const float* __restrict__ Wq, const float* __restrict__ bq,
    const float* __restrict__ Wk, const float* __restrict__ bk,
    const float* __restrict__ Wv, const float* __restrict__ bv)
{
    // xs: 64*65=4160, ws: 64*32=2048 (main). combine: 7*32*30=6720. max 6912.
    __shared__ __align__(16) float sm[6912];
    float* xs = sm;
    float* ws = sm + 4160;

    const int tid = threadIdx.x;
    const int rp  = tid & 31;          // row pair 0..31
    const int kq  = tid >> 5;          // k-slice 0..7
    const int r0  = 2 * rp, r1 = 2 * rp + 1;   // block-local rows
    const int row0 = blockIdx.x * PRJ_ROWS;

    ull accA[15], accB[15];
#pragma unroll
    for (int i = 0; i < 15; i++) { accA[i] = 0ull; accB[i] = 0ull; }

    for (int kc = 0; kc < DIN; kc += 64) {
        __syncthreads();
        // stage x tile: 64 rows x 64 k, coalesced float4 reads
        for (int e = tid; e < 64 * 16; e += 256) {
            int r  = e >> 4;
            int c4 = e & 15;
            float4 v = *reinterpret_cast<const float4*>(
                x + (size_t)(row0 + r) * DIN + kc + c4 * 4);
            float* p = xs + r * XPAD + c4 * 4;
            p[0] = v.x; p[1] = v.y; p[2] = v.z; p[3] = v.w;
        }
        // stage W tile: 64 k x 30 cols (Wq|Wk|Wv)
        for (int e = tid; e < 64 * 30; e += 256) {
            int k = e / 30, j = e % 30;
            float w;
            if (j < 10)      w = Wq[(kc + k) * DK + j];
            else if (j < 20) w = Wk[(kc + k) * DK + (j - 10)];
            else             w = Wv[(kc + k) * DK + (j - 20)];
            ws[k * 32 + j] = w;
        }
        __syncthreads();

#pragma unroll
        for (int kk = 0; kk < 8; kk++) {
            const int k = kq * 8 + kk;
            float xk0 = xs[r0 * XPAD + k];
            float xk1 = xs[r1 * XPAD + k];
            ull xp0 = pack2(xk0, xk0);
            ull xp1 = pack2(xk1, xk1);
            const float4* w4 = reinterpret_cast<const float4*>(ws + k * 32);
#pragma unroll
            for (int i = 0; i < 7; i++) {
                float4 w = w4[i];
                union { float2 f; ull u; } a, b;
                a.f = make_float2(w.x, w.y);
                b.f = make_float2(w.z, w.w);
                fma2(accA[2 * i],     xp0, a.u);
                fma2(accB[2 * i],     xp1, a.u);
                fma2(accA[2 * i + 1], xp0, b.u);
                fma2(accB[2 * i + 1], xp1, b.u);
            }
            {
                union { float2 f; ull u; } c;
                c.f = *reinterpret_cast<const float2*>(ws + k * 32 + 28);
                fma2(accA[14], xp0, c.u);
                fma2(accB[14], xp1, c.u);
            }
        }
    }

    const float rs = 0.4472135954999579f;   // 1/sqrt(5)

    // ---- combine 8 k-slices through smem, one row-set per pass ----
#pragma unroll
    for (int pass = 0; pass < 2; pass++) {
        ull* acc = pass ? accB : accA;
        const int rloc = pass ? r1 : r0;
        __syncthreads();
        if (kq != 0) {
            float* dst = sm + ((kq - 1) * 32 + rp) * 30;
#pragma unroll
            for (int i = 0; i < 15; i++) {
                float lo, hi; unpack2(acc[i], lo, hi);
                dst[2 * i] = lo; dst[2 * i + 1] = hi;
            }
        }
        __syncthreads();
        if (kq == 0) {
            float o[30];
#pragma unroll
            for (int i = 0; i < 15; i++) unpack2(acc[i], o[2 * i], o[2 * i + 1]);
#pragma unroll
            for (int p = 0; p < 7; p++) {
                const float* src = sm + (p * 32 + rp) * 30;
#pragma unroll
                for (int j = 0; j < 30; j++) o[j] += src[j];
            }

            const int grow = row0 + rloc;
            const int b = grow >> 11, n = grow & (Nn - 1);
            float q[10], kk[10], vv[10];
#pragma unroll
            for (int j = 0; j < 10; j++) {
                q[j]  = (o[j]      + bq[j]) * rs;
                kk[j] = (o[j + 10] + bk[j]);
                vv[j] = (o[j + 20] + bv[j]);
            }
#pragma unroll
            for (int h = 0; h < 2; h++) {
                int bh = b * NH + h;
                float* qp = g_Q[bh][n];
                float* kp = g_K[bh][n];
                float* vp = g_V[bh][n];
                *reinterpret_cast<float4*>(qp) = make_float4(q[h*5+0], q[h*5+1], q[h*5+2], q[h*5+3]);
                qp[4] = q[h*5+4];
                *reinterpret_cast<float4*>(kp) = make_float4(kk[h*5+0], kk[h*5+1], kk[h*5+2], kk[h*5+3]);
                kp[4] = kk[h*5+4];
                *reinterpret_cast<float4*>(vp) = make_float4(vv[h*5+0], vv[h*5+1], vv[h*5+2], vv[h*5+3]);
                vp[4] = vv[h*5+4];
            }
        }
    }
}

// =====================================================================
// Kernel 2: causal attention; each thread owns TWO queries (adjacent
// q-tiles 2g and 2g+1) so every K/V LDS is amortized over 2 queries.
// Key range [0, 2g+2) split over 4 blocks (blockIdx.z); partials to g_A.
// sin in [-1,1] => weight = exp(sin(.)), no running max needed.
// Tile modes: 0=full, 1=diagonal, 2=skip.
// =====================================================================
#define TK 128

template <int MA, int MB>
__device__ __forceinline__ void attn_tile2(
    const float* __restrict__ sK, const float* __restrict__ sV,
    const ull* __restrict__ qa2, const ull* __restrict__ qb2, int lim,
    ull accA[5], ull& denA, ull accB[5], ull& denB)
{
    const ull* K2 = reinterpret_cast<const ull*>(sK);   // [d*64 + p]
    const ull* V2 = reinterpret_cast<const ull*>(sV);
#pragma unroll 4
    for (int p = 0; p < TK / 2; p++) {
        ull k0 = K2[p], k1 = K2[64 + p], k2 = K2[128 + p],
            k3 = K2[192 + p], k4 = K2[256 + p];
        ull v0 = V2[p], v1 = V2[64 + p], v2 = V2[128 + p],
            v3 = V2[192 + p], v4 = V2[256 + p];
        if (MA != 2) {
            ull s2 = mul2(qa2[4], k4);
            fma2(s2, qa2[0], k0);
            fma2(s2, qa2[1], k1);
            fma2(s2, qa2[2], k2);
            fma2(s2, qa2[3], k3);
            float s0, s1; unpack2(s2, s0, s1);
            float e0 = __expf(__sinf(s0));
            float e1 = __expf(__sinf(s1));
            if (MA == 1) {
                e0 = (2 * p     <= lim) ? e0 : 0.f;
                e1 = (2 * p + 1 <= lim) ? e1 : 0.f;
            }
            ull e2 = pack2(e0, e1);
            add2(denA, e2);
            fma2(accA[0], e2, v0);
            fma2(accA[1], e2, v1);
            fma2(accA[2], e2, v2);
            fma2(accA[3], e2, v3);
            fma2(accA[4], e2, v4);
        }
        if (MB != 2) {
            ull s2 = mul2(qb2[4], k4);
            fma2(s2, qb2[0], k0);
            fma2(s2, qb2[1], k1);
            fma2(s2, qb2[2], k2);
            fma2(s2, qb2[3], k3);
            float s0, s1; unpack2(s2, s0, s1);
            float e0 = __expf(__sinf(s0));
            float e1 = __expf(__sinf(s1));
            if (MB == 1) {
                e0 = (2 * p     <= lim) ? e0 : 0.f;
                e1 = (2 * p + 1 <= lim) ? e1 : 0.f;
            }
            ull e2 = pack2(e0, e1);
            add2(denB, e2);
            fma2(accB[0], e2, v0);
            fma2(accB[1], e2, v1);
            fma2(accB[2], e2, v2);
            fma2(accB[3], e2, v3);
            fma2(accB[4], e2, v4);
        }
    }
}

__global__ __launch_bounds__(128) void attn_kernel()
{
    __shared__ __align__(16) float sK[5 * TK];
    __shared__ __align__(16) float sV[5 * TK];

    const int tid = threadIdx.x;
    const int g   = (gridDim.x - 1) - blockIdx.x;   // heavy pairs first
    const int bh  = blockIdx.y;
    const int kq  = blockIdx.z;                     // 0..3
    const int qa  = (2 * g) * TK + tid;
    const int qb  = qa + TK;

    const int ntiles = 2 * g + 2;
    const int t0 = (ntiles * kq)       >> 2;
    const int t1 = (ntiles * (kq + 1)) >> 2;

    ull accA[5] = {0,0,0,0,0}, accB[5] = {0,0,0,0,0};
    ull denA = 0ull, denB = 0ull;

    if (t0 < t1) {
        ull qa2[5], qb2[5];
        {
            const float* qp = g_Q[bh][qa];
            float4 qv = *reinterpret_cast<const float4*>(qp);
            float  q4 = qp[4];
            qa2[0] = pack2(qv.x, qv.x); qa2[1] = pack2(qv.y, qv.y);
            qa2[2] = pack2(qv.z, qv.z); qa2[3] = pack2(qv.w, qv.w);
            qa2[4] = pack2(q4, q4);
        }
        {
            const float* qp = g_Q[bh][qb];
            float4 qv = *reinterpret_cast<const float4*>(qp);
            float  q4 = qp[4];
            qb2[0] = pack2(qv.x, qv.x); qb2[1] = pack2(qv.y, qv.y);
            qb2[2] = pack2(qv.z, qv.z); qb2[3] = pack2(qv.w, qv.w);
            qb2[4] = pack2(q4, q4);
        }

        float4 ka, va; float k4, v4;
        {
            const int j = t0 * TK + tid;
            ka = *reinterpret_cast<const float4*>(g_K[bh][j]);
            k4 = g_K[bh][j][4];
            va = *reinterpret_cast<const float4*>(g_V[bh][j]);
            v4 = g_V[bh][j][4];
        }

        for (int kt = t0; kt < t1; kt++) {
            __syncthreads();
            sK[0 * TK + tid] = ka.x; sK[1 * TK + tid] = ka.y;
            sK[2 * TK + tid] = ka.z; sK[3 * TK + tid] = ka.w;
            sK[4 * TK + tid] = k4;
            sV[0 * TK + tid] = va.x; sV[1 * TK + tid] = va.y;
            sV[2 * TK + tid] = va.z; sV[3 * TK + tid] = va.w;
            sV[4 * TK + tid] = v4;
            __syncthreads();

            if (kt + 1 < t1) {
                const int j = (kt + 1) * TK + tid;
                ka = *reinterpret_cast<const float4*>(g_K[bh][j]);
                k4 = g_K[bh][j][4];
                va = *reinterpret_cast<const float4*>(g_V[bh][j]);
                v4 = g_V[bh][j][4];
            }

            if (kt < 2 * g)
                attn_tile2<0, 0>(sK, sV, qa2, qb2, tid, accA, denA, accB, denB);
            else if (kt == 2 * g)
                attn_tile2<1, 0>(sK, sV, qa2, qb2, tid, accA, denA, accB, denB);
            else
                attn_tile2<2, 1>(sK, sV, qa2, qb2, tid, accA, denA, accB, denB);
        }
    }

    // write partials for both queries
#pragma unroll
    for (int w = 0; w < 2; w++) {
        ull* acc = w ? accB : accA;
        ull  dn  = w ? denB : denA;
        int  q   = w ? qb : qa;
        float a[5], den;
#pragma unroll
        for (int d = 0; d < 5; d++) {
            float lo, hi; unpack2(acc[d], lo, hi);
            a[d] = lo + hi;
        }
        { float dl, dh; unpack2(dn, dl, dh); den = dl + dh; }
        float* op = g_A[bh][q][kq];
        *reinterpret_cast<float4*>(op) = make_float4(a[0], a[1], a[2], a[3]);
        op[4] = a[4];
        op[5] = den;
    }
}

// =====================================================================
// Kernel 3: combine attention partials + MLP head.
// 256 threads / 32 rows per block; Wm2 (40KB) in smem; f32x2 packed.
// =====================================================================
#define MR 32

__global__ __launch_bounds__(256) void mlp_kernel(
    const float* __restrict__ Wm1, const float* __restrict__ bm1,
    const float* __restrict__ Wm2, const float* __restrict__ bm2,
    float* __restrict__ out)
{
    __shared__ __align__(16) float w2s[HID * DOUT];  // 40 KB
    __shared__ __align__(16) float h1s[MR * HID];
    __shared__ float cs[MR * DK];

    const int tid  = threadIdx.x;
    const int row0 = blockIdx.x * MR;

    for (int e = tid; e < HID * DOUT / 4; e += 256)
        reinterpret_cast<float4*>(w2s)[e] = reinterpret_cast<const float4*>(Wm2)[e];

    // combine attention partials -> concat c[10] per row
    for (int e = tid; e < MR * DK; e += 256) {
        int r = e / DK, k = e % DK;
        int h = k / DH, d = k % DH;
        int grow = row0 + r;
        int b = grow >> 11, n = grow & (Nn - 1);
        const float* A = g_A[b * NH + h][n][0];   // [4][8] contiguous = 32 floats
        float den = A[5] + A[13] + A[21] + A[29];
        float num = A[d] + A[8 + d] + A[16 + d] + A[24 + d];
        cs[e] = num * __fdividef(1.f, den);
    }
    __syncthreads();

    // h1 = leaky_relu(c @ Wm1 + bm1)
    for (int e = tid; e < MR * HID; e += 256) {
        int r = e / HID, j = e % HID;
        const float* crow = cs + r * DK;
        float s = bm1[j];
#pragma unroll
        for (int k = 0; k < DK; k++)
            s = fmaf(crow[k], Wm1[k * HID + j], s);
        h1s[e] = (s > 0.f) ? s : 0.01f * s;
    }
    __syncthreads();

    const int r  = tid >> 3;
    const int cg = tid & 7;
    ull h2[HID];
#pragma unroll
    for (int k = 0; k < HID; k++) {
        float hk = h1s[r * HID + k];
        h2[k] = pack2(hk, hk);
    }

    float* orow = out + (size_t)(row0 + r) * DOUT;
#pragma unroll 2
    for (int c4 = cg; c4 < DOUT / 4; c4 += 8) {
        union { float4 f; ull u[2]; } a;
        a.f = reinterpret_cast<const float4*>(bm2)[c4];
#pragma unroll
        for (int k = 0; k < HID; k++) {
            union { float4 f; ull u[2]; } w;
            w.f = *reinterpret_cast<const float4*>(w2s + k * DOUT + c4 * 4);
            fma2(a.u[0], h2[k], w.u[0]);
            fma2(a.u[1], h2[k], w.u[1]);
        }
        reinterpret_cast<float4*>(orow)[c4] = a.f;
    }
}

// =====================================================================
extern "C" void kernel_launch(void* const* d_in, const int* in_sizes, int n_in,
                              void* d_out, int out_size)
{
    const float* x   = (const float*)d_in[0];
    const float* Wq  = (const float*)d_in[1];
    const float* bq  = (const float*)d_in[2];
    const float* Wk  = (const float*)d_in[3];
    const float* bk  = (const float*)d_in[4];
    const float* Wv  = (const float*)d_in[5];
    const float* bv  = (const float*)d_in[6];
    const float* Wm1 = (const float*)d_in[7];
    const float* bm1 = (const float*)d_in[8];
    const float* Wm2 = (const float*)d_in[9];
    const float* bm2 = (const float*)d_in[10];

    proj_kernel<<<ROWS / PRJ_ROWS, 256>>>(x, Wq, bq, Wk, bk, Wv, bv);
    attn_kernel<<<dim3(Nn / TK / 2, BH, 4), 128>>>();
    mlp_kernel<<<ROWS / MR, 256>>>(Wm1, bm1, Wm2, bm2, (float*)d_out);
}

// round 6
// speedup vs baseline: 1.1245x; 1.1245x over previous
#include <cuda_runtime.h>

typedef unsigned long long ull;

// ---------------- packed f32x2 PTX helpers ----------------
__device__ __forceinline__ ull pack2(float lo, float hi) {
    ull r; asm("mov.b64 %0, {%1, %2};" : "=l"(r) : "f"(lo), "f"(hi)); return r;
}
__device__ __forceinline__ void unpack2(ull v, float& lo, float& hi) {
    asm("mov.b64 {%0, %1}, %2;" : "=f"(lo), "=f"(hi) : "l"(v));
}
__device__ __forceinline__ void fma2(ull& d, ull a, ull b) {
    asm("fma.rn.f32x2 %0, %1, %2, %0;" : "+l"(d) : "l"(a), "l"(b));
}
__device__ __forceinline__ ull mul2(ull a, ull b) {
    ull d; asm("mul.rn.f32x2 %0, %1, %2;" : "=l"(d) : "l"(a), "l"(b)); return d;
}
__device__ __forceinline__ void add2(ull& d, ull a) {
    asm("add.rn.f32x2 %0, %0, %1;" : "+l"(d) : "l"(a));
}

// ---------------- problem constants ----------------
#define Bn   16
#define Nn   2048
#define DIN  512
#define DK   10
#define NH   2
#define DH   5
#define HID  20
#define DOUT 512
#define BH   (Bn * NH)          // 32
#define ROWS (Bn * Nn)          // 32768
#define KZ   8                  // attention key-split factor

// ---------------- device scratch ----------------
__device__ float g_Q[BH][Nn][8];       // Q pre-scaled by 1/sqrt(5)
__device__ float g_K[BH][Nn][8];
__device__ float g_V[BH][Nn][8];
// attention partials: [bh][q][kz][ a0..a4, den, pad, pad ]
__device__ float g_A[BH][Nn][KZ][8];

// =====================================================================
// Kernel 1: fused QKV projection.
// Grid 512, block 256 = 64 rows x 4 k-slices; 1 row per thread.
// x staged in smem PRE-DUPLICATED as (x,x) ull pairs, odd ull-stride 65
// -> conflict-free LDS.64. W staged [k][32] -> broadcast float4 reads.
// Inner loop: loop-invariant base pointers + compile-time offsets only.
// 4-way k partials combined through smem (aliases x region).
// =====================================================================
#define PR 64
#define XP 65    // ull stride (odd => conflict-free LDS.64)

__global__ __launch_bounds__(256) void proj_kernel(
    const float* __restrict__ x,
    const float* __restrict__ Wq, const float* __restrict__ bq,
    const float* __restrict__ Wk, const float* __restrict__ bk,
    const float* __restrict__ Wv, const float* __restrict__ bv)
{
    // [0, 33280): xs = ull[64*65] ; [33280, 41472): ws = float[64*32]
    __shared__ __align__(16) char smraw[PR * XP * 8 + 64 * 32 * 4];
    ull*   xs = reinterpret_cast<ull*>(smraw);
    float* ws = reinterpret_cast<float*>(smraw + PR * XP * 8);
    float* cm = reinterpret_cast<float*>(smraw);   // combine region (aliases xs)

    const int tid  = threadIdx.x;
    const int row  = tid & 63;
    const int kq   = tid >> 6;                 // 0..3
    const int row0 = blockIdx.x * PR;

    ull acc[15];
#pragma unroll
    for (int i = 0; i < 15; i++) acc[i] = 0ull;

    for (int kc = 0; kc < DIN; kc += 64) {
        __syncthreads();
        // stage x tile: 64 rows x 64 k, coalesced float4 reads, duplicated STS
#pragma unroll
        for (int it = 0; it < 4; it++) {
            int e  = tid + it * 256;
            int r  = e >> 4;
            int c4 = e & 15;
            float4 v = *reinterpret_cast<const float4*>(
                x + (size_t)(row0 + r) * DIN + kc + c4 * 4);
            ull* p = xs + r * XP + c4 * 4;
            p[0] = pack2(v.x, v.x); p[1] = pack2(v.y, v.y);
            p[2] = pack2(v.z, v.z); p[3] = pack2(v.w, v.w);
        }
        // stage W tile: 64 k x 30 cols (Wq|Wk|Wv), padded to 32
#pragma unroll
        for (int it = 0; it < 8; it++) {
            int e = tid + it * 256;
            int k = e >> 5, j = e & 31;
            if (j < 30) {
                float w;
                if (j < 10)      w = Wq[(kc + k) * DK + j];
                else if (j < 20) w = Wk[(kc + k) * DK + (j - 10)];
                else             w = Wv[(kc + k) * DK + (j - 20)];
                ws[e] = w;
            }
        }
        __syncthreads();

        const ull*   xp = xs + row * XP + kq * 16;          // loop-invariant
        const float* wp = ws + kq * 16 * 32;                // loop-invariant
#pragma unroll
        for (int kk = 0; kk < 16; kk++) {
            ull xv = xp[kk];
            const float4* w4 = reinterpret_cast<const float4*>(wp + kk * 32);
#pragma unroll
            for (int i = 0; i < 7; i++) {
                float4 w = w4[i];
                union { float2 f; ull u; } a, b;
                a.f = make_float2(w.x, w.y);
                b.f = make_float2(w.z, w.w);
                fma2(acc[2 * i],     xv, a.u);
                fma2(acc[2 * i + 1], xv, b.u);
            }
            {
                union { float2 f; ull u; } c;
                c.f = *reinterpret_cast<const float2*>(wp + kk * 32 + 28);
                fma2(acc[14], xv, c.u);
            }
        }
    }

    // ---- combine 4 k-slices through smem ----
    __syncthreads();
    if (kq != 0) {
        float* dst = cm + ((kq - 1) * 64 + row) * 30;
#pragma unroll
        for (int i = 0; i < 15; i++) {
            float lo, hi; unpack2(acc[i], lo, hi);
            dst[2 * i] = lo; dst[2 * i + 1] = hi;
        }
    }
    __syncthreads();
    if (kq == 0) {
        float o[30];
#pragma unroll
        for (int i = 0; i < 15; i++) unpack2(acc[i], o[2 * i], o[2 * i + 1]);
#pragma unroll
        for (int p = 0; p < 3; p++) {
            const float* src = cm + (p * 64 + row) * 30;
#pragma unroll
            for (int j = 0; j < 30; j++) o[j] += src[j];
        }

        const int grow = row0 + row;
        const int b = grow >> 11, n = grow & (Nn - 1);
        const float rs = 0.4472135954999579f;   // 1/sqrt(5)

        float q[10], kk[10], vv[10];
#pragma unroll
        for (int j = 0; j < 10; j++) {
            q[j]  = (o[j]      + bq[j]) * rs;
            kk[j] = (o[j + 10] + bk[j]);
            vv[j] = (o[j + 20] + bv[j]);
        }
#pragma unroll
        for (int h = 0; h < 2; h++) {
            int bh = b * NH + h;
            float* qp = g_Q[bh][n];
            float* kp = g_K[bh][n];
            float* vp = g_V[bh][n];
            *reinterpret_cast<float4*>(qp) = make_float4(q[h*5+0], q[h*5+1], q[h*5+2], q[h*5+3]);
            qp[4] = q[h*5+4];
            *reinterpret_cast<float4*>(kp) = make_float4(kk[h*5+0], kk[h*5+1], kk[h*5+2], kk[h*5+3]);
            kp[4] = kk[h*5+4];
            *reinterpret_cast<float4*>(vp) = make_float4(vv[h*5+0], vv[h*5+1], vv[h*5+2], vv[h*5+3]);
            vp[4] = vv[h*5+4];
        }
    }
}

// =====================================================================
// Kernel 2: causal attention; each thread owns FOUR queries (adjacent
// q-tiles 4g..4g+3) so every K/V LDS is amortized over 4 queries ->
// MUFU (sin+exp) becomes the binding pipe.
// Keys [0, 4g+4) tiles split across KZ=8 blocks; partials to g_A.
// sin in [-1,1] => weight = exp(sin(.)), no running max needed.
// CASE: 0 = all-full; c in 1..4 => query c-1 diagonal, <c-1 skip, >c-1 full.
// =====================================================================
#define TK 128

template <int CASE>
__device__ __forceinline__ void attn_tile4(
    const float* __restrict__ sK, const float* __restrict__ sV,
    const ull q2[4][5], int lim, ull acc[4][5], ull den[4])
{
    const ull* K2 = reinterpret_cast<const ull*>(sK);   // [d*64 + p]
    const ull* V2 = reinterpret_cast<const ull*>(sV);
#pragma unroll 4
    for (int p = 0; p < TK / 2; p++) {
        ull k0 = K2[p], k1 = K2[64 + p], k2 = K2[128 + p],
            k3 = K2[192 + p], k4 = K2[256 + p];
        ull v0 = V2[p], v1 = V2[64 + p], v2 = V2[128 + p],
            v3 = V2[192 + p], v4 = V2[256 + p];
#pragma unroll
        for (int i = 0; i < 4; i++) {
            const int mode = (CASE == 0) ? 0
                            : (i == CASE - 1) ? 1
                            : (i <  CASE - 1) ? 2 : 0;
            if (mode != 2) {
                ull s2 = mul2(q2[i][4], k4);
                fma2(s2, q2[i][0], k0);
                fma2(s2, q2[i][1], k1);
                fma2(s2, q2[i][2], k2);
                fma2(s2, q2[i][3], k3);
                float s0, s1; unpack2(s2, s0, s1);
                float e0 = __expf(__sinf(s0));
                float e1 = __expf(__sinf(s1));
                if (mode == 1) {
                    e0 = (2 * p     <= lim) ? e0 : 0.f;
                    e1 = (2 * p + 1 <= lim) ? e1 : 0.f;
                }
                ull e2 = pack2(e0, e1);
                add2(den[i], e2);
                fma2(acc[i][0], e2, v0);
                fma2(acc[i][1], e2, v1);
                fma2(acc[i][2], e2, v2);
                fma2(acc[i][3], e2, v3);
                fma2(acc[i][4], e2, v4);
            }
        }
    }
}

__global__ __launch_bounds__(128) void attn_kernel()
{
    __shared__ __align__(16) float sK[5 * TK];
    __shared__ __align__(16) float sV[5 * TK];

    const int tid = threadIdx.x;
    const int g   = (gridDim.x - 1) - blockIdx.x;   // heavy groups first
    const int bh  = blockIdx.y;
    const int kz  = blockIdx.z;                     // 0..KZ-1

    const int ntiles = 4 * g + 4;
    const int t0 = (ntiles * kz)       / KZ;
    const int t1 = (ntiles * (kz + 1)) / KZ;

    ull acc[4][5], den[4];
#pragma unroll
    for (int i = 0; i < 4; i++) {
        den[i] = 0ull;
#pragma unroll
        for (int d = 0; d < 5; d++) acc[i][d] = 0ull;
    }

    if (t0 < t1) {
        ull q2[4][5];
#pragma unroll
        for (int i = 0; i < 4; i++) {
            const float* qp = g_Q[bh][(4 * g + i) * TK + tid];
            float4 qv = *reinterpret_cast<const float4*>(qp);
            float  q4 = qp[4];
            q2[i][0] = pack2(qv.x, qv.x); q2[i][1] = pack2(qv.y, qv.y);
            q2[i][2] = pack2(qv.z, qv.z); q2[i][3] = pack2(qv.w, qv.w);
            q2[i][4] = pack2(q4, q4);
        }

        float4 ka, va; float k4, v4;
        {
            const int j = t0 * TK + tid;
            ka = *reinterpret_cast<const float4*>(g_K[bh][j]);
            k4 = g_K[bh][j][4];
            va = *reinterpret_cast<const float4*>(g_V[bh][j]);
            v4 = g_V[bh][j][4];
        }

        for (int kt = t0; kt < t1; kt++) {
            __syncthreads();
            sK[0 * TK + tid] = ka.x; sK[1 * TK + tid] = ka.y;
            sK[2 * TK + tid] = ka.z; sK[3 * TK + tid] = ka.w;
            sK[4 * TK + tid] = k4;
            sV[0 * TK + tid] = va.x; sV[1 * TK + tid] = va.y;
            sV[2 * TK + tid] = va.z; sV[3 * TK + tid] = va.w;
            sV[4 * TK + tid] = v4;
            __syncthreads();

            if (kt + 1 < t1) {   // prefetch next tile
                const int j = (kt + 1) * TK + tid;
                ka = *reinterpret_cast<const float4*>(g_K[bh][j]);
                k4 = g_K[bh][j][4];
                va = *reinterpret_cast<const float4*>(g_V[bh][j]);
                v4 = g_V[bh][j][4];
            }

            const int cs = kt - 4 * g;
            if (cs < 0)       attn_tile4<0>(sK, sV, q2, tid, acc, den);
            else if (cs == 0) attn_tile4<1>(sK, sV, q2, tid, acc, den);
            else if (cs == 1) attn_tile4<2>(sK, sV, q2, tid, acc, den);
            else if (cs == 2) attn_tile4<3>(sK, sV, q2, tid, acc, den);
            else              attn_tile4<4>(sK, sV, q2, tid, acc, den);
        }
    }

    // write partials for all 4 queries (zeros when slice empty)
#pragma unroll
    for (int i = 0; i < 4; i++) {
        float a[5], dn;
#pragma unroll
        for (int d = 0; d < 5; d++) {
            float lo, hi; unpack2(acc[i][d], lo, hi);
            a[d] = lo + hi;
        }
        { float dl, dh; unpack2(den[i], dl, dh); dn = dl + dh; }
        float* op = g_A[bh][(4 * g + i) * TK + tid][kz];
        *reinterpret_cast<float4*>(op) = make_float4(a[0], a[1], a[2], a[3]);
        op[4] = a[4];
        op[5] = dn;
    }
}

// =====================================================================
// Kernel 3: combine attention partials + MLP head.
// 256 threads / 32 rows per block; Wm2 (40KB) in smem; f32x2 packed.
// =====================================================================
#define MR 32

__global__ __launch_bounds__(256) void mlp_kernel(
    const float* __restrict__ Wm1, const float* __restrict__ bm1,
    const float* __restrict__ Wm2, const float* __restrict__ bm2,
    float* __restrict__ out)
{
    __shared__ __align__(16) float w2s[HID * DOUT];  // 40 KB
    __shared__ __align__(16) float h1s[MR * HID];
    __shared__ float cs[MR * DK];

    const int tid  = threadIdx.x;
    const int row0 = blockIdx.x * MR;

    for (int e = tid; e < HID * DOUT / 4; e += 256)
        reinterpret_cast<float4*>(w2s)[e] = reinterpret_cast<const float4*>(Wm2)[e];

    // combine attention partials -> concat c[10] per row
    for (int e = tid; e < MR * DK; e += 256) {
        int r = e / DK, k = e % DK;
        int h = k / DH, d = k % DH;
        int grow = row0 + r;
        int b = grow >> 11, n = grow & (Nn - 1);
        const float* A = g_A[b * NH + h][n][0];   // [KZ][8] contiguous
        float den = 0.f, num = 0.f;
#pragma unroll
        for (int s = 0; s < KZ; s++) {
            num += A[8 * s + d];
            den += A[8 * s + 5];
        }
        cs[e] = num * __fdividef(1.f, den);
    }
    __syncthreads();

    // h1 = leaky_relu(c @ Wm1 + bm1)
    for (int e = tid; e < MR * HID; e += 256) {
        int r = e / HID, j = e % HID;
        const float* crow = cs + r * DK;
        float s = bm1[j];
#pragma unroll
        for (int k = 0; k < DK; k++)
            s = fmaf(crow[k], Wm1[k * HID + j], s);
        h1s[e] = (s > 0.f) ? s : 0.01f * s;
    }
    __syncthreads();

    const int r  = tid >> 3;
    const int cg = tid & 7;
    ull h2[HID];
#pragma unroll
    for (int k = 0; k < HID; k++) {
        float hk = h1s[r * HID + k];
        h2[k] = pack2(hk, hk);
    }

    float* orow = out + (size_t)(row0 + r) * DOUT;
#pragma unroll 2
    for (int c4 = cg; c4 < DOUT / 4; c4 += 8) {
        union { float4 f; ull u[2]; } a;
        a.f = reinterpret_cast<const float4*>(bm2)[c4];
#pragma unroll
        for (int k = 0; k < HID; k++) {
            union { float4 f; ull u[2]; } w;
            w.f = *reinterpret_cast<const float4*>(w2s + k * DOUT + c4 * 4);
            fma2(a.u[0], h2[k], w.u[0]);
            fma2(a.u[1], h2[k], w.u[1]);
        }
        reinterpret_cast<float4*>(orow)[c4] = a.f;
    }
}

// =====================================================================
extern "C" void kernel_launch(void* const* d_in, const int* in_sizes, int n_in,
                              void* d_out, int out_size)
{
    const float* x   = (const float*)d_in[0];
    const float* Wq  = (const float*)d_in[1];
    const float* bq  = (const float*)d_in[2];
    const float* Wk  = (const float*)d_in[3];
    const float* bk  = (const float*)d_in[4];
    const float* Wv  = (const float*)d_in[5];
    const float* bv  = (const float*)d_in[6];
    const float* Wm1 = (const float*)d_in[7];
    const float* bm1 = (const float*)d_in[8];
    const float* Wm2 = (const float*)d_in[9];
    const float* bm2 = (const float*)d_in[10];

    proj_kernel<<<ROWS / PR, 256>>>(x, Wq, bq, Wk, bk, Wv, bv);
    attn_kernel<<<dim3(Nn / TK / 4, BH, KZ), 128>>>();
    mlp_kernel<<<ROWS / MR, 256>>>(Wm1, bm1, Wm2, bm2, (float*)d_out);
}

// round 7
// speedup vs baseline: 1.3998x; 1.2448x over previous
#include <cuda_runtime.h>

typedef unsigned long long ull;

// ---------------- packed f32x2 PTX helpers ----------------
__device__ __forceinline__ ull pack2(float lo, float hi) {
    ull r; asm("mov.b64 %0, {%1, %2};" : "=l"(r) : "f"(lo), "f"(hi)); return r;
}
__device__ __forceinline__ void unpack2(ull v, float& lo, float& hi) {
    asm("mov.b64 {%0, %1}, %2;" : "=f"(lo), "=f"(hi) : "l"(v));
}
__device__ __forceinline__ void fma2(ull& d, ull a, ull b) {
    asm("fma.rn.f32x2 %0, %1, %2, %0;" : "+l"(d) : "l"(a), "l"(b));
}
__device__ __forceinline__ ull mul2(ull a, ull b) {
    ull d; asm("mul.rn.f32x2 %0, %1, %2;" : "=l"(d) : "l"(a), "l"(b)); return d;
}
__device__ __forceinline__ void add2(ull& d, ull a) {
    asm("add.rn.f32x2 %0, %0, %1;" : "+l"(d) : "l"(a));
}

// ---------------- problem constants ----------------
#define Bn   16
#define Nn   2048
#define DIN  512
#define DK   10
#define NH   2
#define DH   5
#define HID  20
#define DOUT 512
#define BH   (Bn * NH)          // 32
#define ROWS (Bn * Nn)          // 32768
#define KZ   8                  // attention key-split factor

// ---------------- device scratch ----------------
__device__ float g_Q[BH][Nn][8];       // Q pre-scaled by 1/sqrt(5)
__device__ float g_K[BH][Nn][8];
__device__ float g_V[BH][Nn][8];
// attention partials: [bh][q][kz][ a0..a4, den, pad, pad ]
__device__ float g_A[BH][Nn][KZ][8];

// =====================================================================
// Kernel 1: fused QKV projection (R3 topology + register double-buffer).
// Grid 256, block 256 = 128 rows x 2 k-halves; 1 row per thread.
// Per 64-k chunk: x+W for chunk c+1 are LDG'd into registers WHILE chunk c
// is being computed -> no barrier-coupled DRAM exposure.
// xs stride 65 floats -> conflict-free scalar LDS; W broadcast float4 LDS.
// =====================================================================
#define PR   128
#define XPAD 65

__global__ __launch_bounds__(256) void proj_kernel(
    const float* __restrict__ x,
    const float* __restrict__ Wq, const float* __restrict__ bq,
    const float* __restrict__ Wk, const float* __restrict__ bk,
    const float* __restrict__ Wv, const float* __restrict__ bv)
{
    __shared__ float xs[PR * XPAD];                 // 33.3 KB
    __shared__ __align__(16) float ws[64 * 32];     // 8 KB

    const int tid  = threadIdx.x;
    const int row  = tid & 127;
    const int kh   = tid >> 7;          // 0 or 1
    const int row0 = blockIdx.x * PR;

    ull acc[15];
#pragma unroll
    for (int i = 0; i < 15; i++) acc[i] = 0ull;

    float4 xr[8];
    float  wr[8];

    // ---- prefetch chunk 0 into registers ----
#pragma unroll
    for (int it = 0; it < 8; it++) {
        int e  = tid + it * 256;
        int r  = e >> 4;
        int c4 = e & 15;
        xr[it] = *reinterpret_cast<const float4*>(
            x + (size_t)(row0 + r) * DIN + c4 * 4);
    }
#pragma unroll
    for (int it = 0; it < 8; it++) {
        int e = tid + it * 256;
        if (e < 64 * 30) {
            int k = e / 30, j = e % 30;
            wr[it] = (j < 10) ? Wq[k * DK + j]
                   : (j < 20) ? Wk[k * DK + (j - 10)]
                              : Wv[k * DK + (j - 20)];
        }
    }

    for (int c = 0; c < 8; c++) {
        __syncthreads();   // previous chunk's compute done
        // store registers -> smem
#pragma unroll
        for (int it = 0; it < 8; it++) {
            int e  = tid + it * 256;
            int r  = e >> 4;
            int c4 = e & 15;
            float* p = xs + r * XPAD + c4 * 4;
            p[0] = xr[it].x; p[1] = xr[it].y; p[2] = xr[it].z; p[3] = xr[it].w;
        }
#pragma unroll
        for (int it = 0; it < 8; it++) {
            int e = tid + it * 256;
            if (e < 64 * 30) {
                int k = e / 30, j = e % 30;
                ws[k * 32 + j] = wr[it];
            }
        }
        __syncthreads();

        // prefetch chunk c+1 into registers (overlaps compute below)
        if (c < 7) {
            const int kc = (c + 1) * 64;
#pragma unroll
            for (int it = 0; it < 8; it++) {
                int e  = tid + it * 256;
                int r  = e >> 4;
                int c4 = e & 15;
                xr[it] = *reinterpret_cast<const float4*>(
                    x + (size_t)(row0 + r) * DIN + kc + c4 * 4);
            }
#pragma unroll
            for (int it = 0; it < 8; it++) {
                int e = tid + it * 256;
                if (e < 64 * 30) {
                    int k = e / 30, j = e % 30;
                    wr[it] = (j < 10) ? Wq[(kc + k) * DK + j]
                           : (j < 20) ? Wk[(kc + k) * DK + (j - 10)]
                                      : Wv[(kc + k) * DK + (j - 20)];
                }
            }
        }

        // ---- compute this chunk: 32 k per thread (its half) ----
        const float* xp = xs + row * XPAD + kh * 32;
        const float* wp = ws + (kh * 32) * 32;
#pragma unroll
        for (int kk = 0; kk < 32; kk++) {
            float xk = xp[kk];
            ull  xv = pack2(xk, xk);
            const float4* w4 = reinterpret_cast<const float4*>(wp + kk * 32);
#pragma unroll
            for (int i = 0; i < 7; i++) {
                float4 w = w4[i];
                union { float2 f; ull u; } a, b;
                a.f = make_float2(w.x, w.y);
                b.f = make_float2(w.z, w.w);
                fma2(acc[2 * i],     xv, a.u);
                fma2(acc[2 * i + 1], xv, b.u);
            }
            {
                union { float2 f; ull u; } cc;
                cc.f = *reinterpret_cast<const float2*>(wp + kk * 32 + 28);
                fma2(acc[14], xv, cc.u);
            }
        }
    }

    // ---- combine the two k-halves through smem (alias xs) ----
    __syncthreads();
    if (kh == 1) {
        float* dst = xs + row * 30;
#pragma unroll
        for (int i = 0; i < 15; i++) {
            float lo, hi; unpack2(acc[i], lo, hi);
            dst[2 * i] = lo; dst[2 * i + 1] = hi;
        }
    }
    __syncthreads();
    if (kh == 0) {
        float o[30];
        const float* src = xs + row * 30;
#pragma unroll
        for (int i = 0; i < 15; i++) {
            float lo, hi; unpack2(acc[i], lo, hi);
            o[2 * i]     = lo + src[2 * i];
            o[2 * i + 1] = hi + src[2 * i + 1];
        }

        const int grow = row0 + row;
        const int b = grow >> 11, n = grow & (Nn - 1);
        const float rs = 0.4472135954999579f;   // 1/sqrt(5)

        float q[10], kk[10], vv[10];
#pragma unroll
        for (int j = 0; j < 10; j++) {
            q[j]  = (o[j]      + bq[j]) * rs;
            kk[j] = (o[j + 10] + bk[j]);
            vv[j] = (o[j + 20] + bv[j]);
        }
#pragma unroll
        for (int h = 0; h < 2; h++) {
            int bh = b * NH + h;
            float* qp = g_Q[bh][n];
            float* kp = g_K[bh][n];
            float* vp = g_V[bh][n];
            *reinterpret_cast<float4*>(qp) = make_float4(q[h*5+0], q[h*5+1], q[h*5+2], q[h*5+3]);
            qp[4] = q[h*5+4];
            *reinterpret_cast<float4*>(kp) = make_float4(kk[h*5+0], kk[h*5+1], kk[h*5+2], kk[h*5+3]);
            kp[4] = kk[h*5+4];
            *reinterpret_cast<float4*>(vp) = make_float4(vv[h*5+0], vv[h*5+1], vv[h*5+2], vv[h*5+3]);
            vp[4] = vv[h*5+4];
        }
    }
}

// =====================================================================
// Kernel 2: causal attention; each thread owns FOUR queries (adjacent
// q-tiles 4g..4g+3); K/V LDS amortized over 4 queries; MUFU-paced.
// Keys [0, 4g+4) tiles split across KZ=8 blocks; partials to g_A.
// sin in [-1,1] => weight = exp(sin(.)), no running max needed.
// =====================================================================
#define TK 128

template <int CASE>
__device__ __forceinline__ void attn_tile4(
    const float* __restrict__ sK, const float* __restrict__ sV,
    const ull q2[4][5], int lim, ull acc[4][5], ull den[4])
{
    const ull* K2 = reinterpret_cast<const ull*>(sK);   // [d*64 + p]
    const ull* V2 = reinterpret_cast<const ull*>(sV);
#pragma unroll 4
    for (int p = 0; p < TK / 2; p++) {
        ull k0 = K2[p], k1 = K2[64 + p], k2 = K2[128 + p],
            k3 = K2[192 + p], k4 = K2[256 + p];
        ull v0 = V2[p], v1 = V2[64 + p], v2 = V2[128 + p],
            v3 = V2[192 + p], v4 = V2[256 + p];
#pragma unroll
        for (int i = 0; i < 4; i++) {
            const int mode = (CASE == 0) ? 0
                            : (i == CASE - 1) ? 1
                            : (i <  CASE - 1) ? 2 : 0;
            if (mode != 2) {
                ull s2 = mul2(q2[i][4], k4);
                fma2(s2, q2[i][0], k0);
                fma2(s2, q2[i][1], k1);
                fma2(s2, q2[i][2], k2);
                fma2(s2, q2[i][3], k3);
                float s0, s1; unpack2(s2, s0, s1);
                float e0 = __expf(__sinf(s0));
                float e1 = __expf(__sinf(s1));
                if (mode == 1) {
                    e0 = (2 * p     <= lim) ? e0 : 0.f;
                    e1 = (2 * p + 1 <= lim) ? e1 : 0.f;
                }
                ull e2 = pack2(e0, e1);
                add2(den[i], e2);
                fma2(acc[i][0], e2, v0);
                fma2(acc[i][1], e2, v1);
                fma2(acc[i][2], e2, v2);
                fma2(acc[i][3], e2, v3);
                fma2(acc[i][4], e2, v4);
            }
        }
    }
}

__global__ __launch_bounds__(128) void attn_kernel()
{
    __shared__ __align__(16) float sK[5 * TK];
    __shared__ __align__(16) float sV[5 * TK];

    const int tid = threadIdx.x;
    const int g   = (gridDim.x - 1) - blockIdx.x;   // heavy groups first
    const int bh  = blockIdx.y;
    const int kz  = blockIdx.z;                     // 0..KZ-1

    const int ntiles = 4 * g + 4;
    const int t0 = (ntiles * kz)       / KZ;
    const int t1 = (ntiles * (kz + 1)) / KZ;

    ull acc[4][5], den[4];
#pragma unroll
    for (int i = 0; i < 4; i++) {
        den[i] = 0ull;
#pragma unroll
        for (int d = 0; d < 5; d++) acc[i][d] = 0ull;
    }

    if (t0 < t1) {
        ull q2[4][5];
#pragma unroll
        for (int i = 0; i < 4; i++) {
            const float* qp = g_Q[bh][(4 * g + i) * TK + tid];
            float4 qv = *reinterpret_cast<const float4*>(qp);
            float  q4 = qp[4];
            q2[i][0] = pack2(qv.x, qv.x); q2[i][1] = pack2(qv.y, qv.y);
            q2[i][2] = pack2(qv.z, qv.z); q2[i][3] = pack2(qv.w, qv.w);
            q2[i][4] = pack2(q4, q4);
        }

        float4 ka, va; float k4, v4;
        {
            const int j = t0 * TK + tid;
            ka = *reinterpret_cast<const float4*>(g_K[bh][j]);
            k4 = g_K[bh][j][4];
            va = *reinterpret_cast<const float4*>(g_V[bh][j]);
            v4 = g_V[bh][j][4];
        }

        for (int kt = t0; kt < t1; kt++) {
            __syncthreads();
            sK[0 * TK + tid] = ka.x; sK[1 * TK + tid] = ka.y;
            sK[2 * TK + tid] = ka.z; sK[3 * TK + tid] = ka.w;
            sK[4 * TK + tid] = k4;
            sV[0 * TK + tid] = va.x; sV[1 * TK + tid] = va.y;
            sV[2 * TK + tid] = va.z; sV[3 * TK + tid] = va.w;
            sV[4 * TK + tid] = v4;
            __syncthreads();

            if (kt + 1 < t1) {   // prefetch next tile
                const int j = (kt + 1) * TK + tid;
                ka = *reinterpret_cast<const float4*>(g_K[bh][j]);
                k4 = g_K[bh][j][4];
                va = *reinterpret_cast<const float4*>(g_V[bh][j]);
                v4 = g_V[bh][j][4];
            }

            const int cs = kt - 4 * g;
            if (cs < 0)       attn_tile4<0>(sK, sV, q2, tid, acc, den);
            else if (cs == 0) attn_tile4<1>(sK, sV, q2, tid, acc, den);
            else if (cs == 1) attn_tile4<2>(sK, sV, q2, tid, acc, den);
            else if (cs == 2) attn_tile4<3>(sK, sV, q2, tid, acc, den);
            else              attn_tile4<4>(sK, sV, q2, tid, acc, den);
        }
    }

    // write partials for all 4 queries (zeros when slice empty)
#pragma unroll
    for (int i = 0; i < 4; i++) {
        float a[5], dn;
#pragma unroll
        for (int d = 0; d < 5; d++) {
            float lo, hi; unpack2(acc[i][d], lo, hi);
            a[d] = lo + hi;
        }
        { float dl, dh; unpack2(den[i], dl, dh); dn = dl + dh; }
        float* op = g_A[bh][(4 * g + i) * TK + tid][kz];
        *reinterpret_cast<float4*>(op) = make_float4(a[0], a[1], a[2], a[3]);
        op[4] = a[4];
        op[5] = dn;
    }
}

// =====================================================================
// Kernel 3: combine attention partials + MLP head.
// 256 threads / 64 rows per block (halved block count vs before);
// Wm2 (40KB) in smem; f32x2 packed; thread = (row, 1-of-4 col groups).
// =====================================================================
#define MR 64

__global__ __launch_bounds__(256) void mlp_kernel(
    const float* __restrict__ Wm1, const float* __restrict__ bm1,
    const float* __restrict__ Wm2, const float* __restrict__ bm2,
    float* __restrict__ out)
{
    __shared__ __align__(16) float w2s[HID * DOUT];  // 40 KB
    __shared__ __align__(16) float h1s[MR * HID];    // 5 KB
    __shared__ float cs[MR * DK];                    // 2.5 KB

    const int tid  = threadIdx.x;
    const int row0 = blockIdx.x * MR;

    for (int e = tid; e < HID * DOUT / 4; e += 256)
        reinterpret_cast<float4*>(w2s)[e] = reinterpret_cast<const float4*>(Wm2)[e];

    // combine attention partials -> concat c[10] per row
    for (int e = tid; e < MR * DK; e += 256) {
        int r = e / DK, k = e % DK;
        int h = k / DH, d = k % DH;
        int grow = row0 + r;
        int b = grow >> 11, n = grow & (Nn - 1);
        const float* A = g_A[b * NH + h][n][0];   // [KZ][8] contiguous
        float den = 0.f, num = 0.f;
#pragma unroll
        for (int s = 0; s < KZ; s++) {
            num += A[8 * s + d];
            den += A[8 * s + 5];
        }
        cs[e] = num * __fdividef(1.f, den);
    }
    __syncthreads();

    // h1 = leaky_relu(c @ Wm1 + bm1)
    for (int e = tid; e < MR * HID; e += 256) {
        int r = e / HID, j = e % HID;
        const float* crow = cs + r * DK;
        float s = bm1[j];
#pragma unroll
        for (int k = 0; k < DK; k++)
            s = fmaf(crow[k], Wm1[k * HID + j], s);
        h1s[e] = (s > 0.f) ? s : 0.01f * s;
    }
    __syncthreads();

    const int r  = tid >> 2;   // 0..63
    const int cg = tid & 3;    // 0..3
    ull h2[HID];
#pragma unroll
    for (int k = 0; k < HID; k++) {
        float hk = h1s[r * HID + k];
        h2[k] = pack2(hk, hk);
    }

    float* orow = out + (size_t)(row0 + r) * DOUT;
#pragma unroll 2
    for (int c4 = cg; c4 < DOUT / 4; c4 += 4) {
        union { float4 f; ull u[2]; } a;
        a.f = reinterpret_cast<const float4*>(bm2)[c4];
#pragma unroll
        for (int k = 0; k < HID; k++) {
            union { float4 f; ull u[2]; } w;
            w.f = *reinterpret_cast<const float4*>(w2s + k * DOUT + c4 * 4);
            fma2(a.u[0], h2[k], w.u[0]);
            fma2(a.u[1], h2[k], w.u[1]);
        }
        reinterpret_cast<float4*>(orow)[c4] = a.f;
    }
}

// =====================================================================
extern "C" void kernel_launch(void* const* d_in, const int* in_sizes, int n_in,
                              void* d_out, int out_size)
{
    const float* x   = (const float*)d_in[0];
    const float* Wq  = (const float*)d_in[1];
    const float* bq  = (const float*)d_in[2];
    const float* Wk  = (const float*)d_in[3];
    const float* bk  = (const float*)d_in[4];
    const float* Wv  = (const float*)d_in[5];
    const float* bv  = (const float*)d_in[6];
    const float* Wm1 = (const float*)d_in[7];
    const float* bm1 = (const float*)d_in[8];
    const float* Wm2 = (const float*)d_in[9];
    const float* bm2 = (const float*)d_in[10];

    proj_kernel<<<ROWS / PR, 256>>>(x, Wq, bq, Wk, bk, Wv, bv);
    attn_kernel<<<dim3(Nn / TK / 4, BH, KZ), 128>>>();
    mlp_kernel<<<ROWS / MR, 256>>>(Wm1, bm1, Wm2, bm2, (float*)d_out);
}

// round 9
// speedup vs baseline: 1.5494x; 1.1068x over previous
#include <cuda_runtime.h>
#include <cuda_bf16.h>
#include <cstdint>

typedef unsigned long long ull;

// ---------------- packed f32x2 helpers (attn/mlp) ----------------
__device__ __forceinline__ ull pack2(float lo, float hi) {
    ull r; asm("mov.b64 %0, {%1, %2};" : "=l"(r) : "f"(lo), "f"(hi)); return r;
}
__device__ __forceinline__ void unpack2(ull v, float& lo, float& hi) {
    asm("mov.b64 {%0, %1}, %2;" : "=f"(lo), "=f"(hi) : "l"(v));
}
__device__ __forceinline__ void fma2(ull& d, ull a, ull b) {
    asm("fma.rn.f32x2 %0, %1, %2, %0;" : "+l"(d) : "l"(a), "l"(b));
}
__device__ __forceinline__ ull mul2(ull a, ull b) {
    ull d; asm("mul.rn.f32x2 %0, %1, %2;" : "=l"(d) : "l"(a), "l"(b)); return d;
}
__device__ __forceinline__ void add2(ull& d, ull a) {
    asm("add.rn.f32x2 %0, %0, %1;" : "+l"(d) : "l"(a));
}

// ---------------- HMMA helpers (family-portable: sm_80+) ----------------
__device__ __forceinline__ uint32_t smem_u32(const void* p) {
    uint32_t a;
    asm("{ .reg .u64 t; cvta.to.shared.u64 t, %1; cvt.u32.u64 %0, t; }" : "=r"(a) : "l"(p));
    return a;
}
__device__ __forceinline__ void ldsm4(uint32_t r[4], uint32_t addr) {
    asm volatile("ldmatrix.sync.aligned.m8n8.x4.shared.b16 {%0,%1,%2,%3}, [%4];"
        : "=r"(r[0]), "=r"(r[1]), "=r"(r[2]), "=r"(r[3]) : "r"(addr));
}
__device__ __forceinline__ void mma_bf16(float c[4], const uint32_t a[4], uint32_t b0, uint32_t b1) {
    asm volatile("mma.sync.aligned.m16n8k16.row.col.f32.bf16.bf16.f32 "
        "{%0,%1,%2,%3}, {%4,%5,%6,%7}, {%8,%9}, {%0,%1,%2,%3};"
        : "+f"(c[0]), "+f"(c[1]), "+f"(c[2]), "+f"(c[3])
        : "r"(a[0]), "r"(a[1]), "r"(a[2]), "r"(a[3]), "r"(b0), "r"(b1));
}
__device__ __forceinline__ uint32_t pbf2(float lo, float hi) {   // low half = lo
    uint32_t r; asm("cvt.rn.bf16x2.f32 %0, %1, %2;" : "=r"(r) : "f"(hi), "f"(lo)); return r;
}
__device__ __forceinline__ unsigned short bf16rn(float f) {
    unsigned short u; asm("cvt.rn.bf16.f32 %0, %1;" : "=h"(u) : "f"(f)); return u;
}

// ---------------- problem constants ----------------
#define Bn   16
#define Nn   2048
#define DIN  512
#define DK   10
#define NH   2
#define DH   5
#define HID  20
#define DOUT 512
#define ROWS (Bn * Nn)             // 32768
#define KZ   8

// ---------------- device scratch ----------------
__device__ float g_Q[32][Nn][8];       // Q pre-scaled by 1/sqrt(5)
__device__ float g_K[32][Nn][8];
__device__ float g_V[32][Nn][8];
__device__ float g_A[32][Nn][KZ][8];

// =====================================================================
// Kernel 1: QKV projection on HMMA (mma.sync m16n8k16, bf16 split).
// Block = 128 rows x N32 x K512 (8 chunks of 64). 8 warps: warp w owns
// m-strip [16w, 16w+16), 4 n8 tiles, fp32 C in registers.
// x/W split: v = hi(trunc bf16) + lo(bf16); D = Ahi*Bhi+Ahi*Blo+Alo*Bhi.
// xs: bf16 [128 rows][72] (hi & lo planes); ws: bf16 [32 n][72] per plane.
// ldmatrix A frags; B frags via conflict-free LDS.32 (banks 4n+j).
// =====================================================================
#define XSTR 72              // bf16 row stride (144 B: 8-row ldmatrix walk hits 8 distinct banks)
#define XH_OFF 0
#define XL_OFF (128 * XSTR * 2)                 // 18432
#define WH_OFF (2 * 128 * XSTR * 2)             // 36864
#define WL_OFF (WH_OFF + 32 * XSTR * 2)         // 41472
#define SM_TOT (WL_OFF + 32 * XSTR * 2)         // 46080

__global__ __launch_bounds__(256) void proj_tc(
    const float* __restrict__ x,
    const float* __restrict__ Wq, const float* __restrict__ bq,
    const float* __restrict__ Wk, const float* __restrict__ bk,
    const float* __restrict__ Wv, const float* __restrict__ bv)
{
    __shared__ __align__(16) char sm[SM_TOT];
    const uint32_t sb = smem_u32(sm);

    const int tid  = threadIdx.x;
    const int wid  = tid >> 5;
    const int lane = tid & 31;
    const int row0 = blockIdx.x * 128;
    const int m0   = wid * 16;

    float C[4][4];
#pragma unroll
    for (int t = 0; t < 4; t++)
#pragma unroll
        for (int i = 0; i < 4; i++) C[t][i] = 0.f;

    // ---- register prefetch of chunk 0 ----
    float4 xr[8];
    float  wr[8];
#pragma unroll
    for (int it = 0; it < 8; it++) {
        int e = tid + it * 256;
        int r = e >> 4, c4 = e & 15;
        xr[it] = *reinterpret_cast<const float4*>(x + (size_t)(row0 + r) * DIN + c4 * 4);
    }
#pragma unroll
    for (int it = 0; it < 8; it++) {
        int e = tid + it * 256;
        int k = e >> 5, j = e & 31;
        wr[it] = (j < 10) ? Wq[k * DK + j]
               : (j < 20) ? Wk[k * DK + (j - 10)]
               : (j < 30) ? Wv[k * DK + (j - 20)] : 0.f;
    }

    // ldmatrix per-thread source address components
    const int arow = lane & 15;          // row within m16 strip
    const int agrp = lane >> 4;          // 0: k0-7, 1: k8-15 (16B offset)
    // B frag address components
    const int bn = lane >> 2;            // n within n8 tile
    const int bk0 = (lane & 3) * 2;      // k within k16 step

    for (int c = 0; c < 8; c++) {
        __syncthreads();   // previous chunk's MMA done
        // ---- stage x chunk as bf16 hi/lo ----
#pragma unroll
        for (int it = 0; it < 8; it++) {
            int e = tid + it * 256;
            int r = e >> 4, c4 = e & 15;
            float4 v = xr[it];
            uint32_t b0 = __float_as_uint(v.x), b1 = __float_as_uint(v.y);
            uint32_t b2 = __float_as_uint(v.z), b3 = __float_as_uint(v.w);
            uint32_t h01 = __byte_perm(b0, b1, 0x7632);
            uint32_t h23 = __byte_perm(b2, b3, 0x7632);
            float l0 = v.x - __uint_as_float(b0 & 0xFFFF0000u);
            float l1 = v.y - __uint_as_float(b1 & 0xFFFF0000u);
            float l2 = v.z - __uint_as_float(b2 & 0xFFFF0000u);
            float l3 = v.w - __uint_as_float(b3 & 0xFFFF0000u);
            uint32_t off = (r * XSTR + c4 * 4) * 2;
            *reinterpret_cast<uint2*>(sm + XH_OFF + off) = make_uint2(h01, h23);
            *reinterpret_cast<uint2*>(sm + XL_OFF + off) =
                make_uint2(pbf2(l0, l1), pbf2(l2, l3));
        }
        // ---- stage W chunk transposed [n][k] as bf16 hi/lo ----
#pragma unroll
        for (int it = 0; it < 8; it++) {
            int e = tid + it * 256;
            int k = e >> 5, j = e & 31;
            float w = wr[it];
            uint32_t wb = __float_as_uint(w);
            unsigned short whi = (unsigned short)(wb >> 16);
            unsigned short wlo = bf16rn(w - __uint_as_float(wb & 0xFFFF0000u));
            uint32_t off = (j * XSTR + k) * 2;
            *reinterpret_cast<unsigned short*>(sm + WH_OFF + off) = whi;
            *reinterpret_cast<unsigned short*>(sm + WL_OFF + off) = wlo;
        }
        __syncthreads();

        // ---- prefetch next chunk (overlaps MMA below) ----
        if (c < 7) {
            const int kc = (c + 1) * 64;
#pragma unroll
            for (int it = 0; it < 8; it++) {
                int e = tid + it * 256;
                int r = e >> 4, c4 = e & 15;
                xr[it] = *reinterpret_cast<const float4*>(
                    x + (size_t)(row0 + r) * DIN + kc + c4 * 4);
            }
#pragma unroll
            for (int it = 0; it < 8; it++) {
                int e = tid + it * 256;
                int k = kc + (e >> 5), j = e & 31;
                wr[it] = (j < 10) ? Wq[k * DK + j]
                       : (j < 20) ? Wk[k * DK + (j - 10)]
                       : (j < 30) ? Wv[k * DK + (j - 20)] : 0.f;
            }
        }

        // ---- 4 k16 steps x (Ahi*Bhi + Ahi*Blo + Alo*Bhi) ----
#pragma unroll
        for (int ks = 0; ks < 4; ks++) {
            uint32_t ah[4], al[4];
            uint32_t abase = (m0 + arow) * (XSTR * 2) + ks * 32 + agrp * 16;
            ldsm4(ah, sb + XH_OFF + abase);
            ldsm4(al, sb + XL_OFF + abase);
#pragma unroll
            for (int t = 0; t < 4; t++) {
                uint32_t boff = ((bn + t * 8) * XSTR + ks * 16 + bk0) * 2;
                uint32_t bh0 = *reinterpret_cast<const uint32_t*>(sm + WH_OFF + boff);
                uint32_t bh1 = *reinterpret_cast<const uint32_t*>(sm + WH_OFF + boff + 16);
                uint32_t bl0 = *reinterpret_cast<const uint32_t*>(sm + WL_OFF + boff);
                uint32_t bl1 = *reinterpret_cast<const uint32_t*>(sm + WL_OFF + boff + 16);
                mma_bf16(C[t], ah, bh0, bh1);
                mma_bf16(C[t], ah, bl0, bl1);
                mma_bf16(C[t], al, bh0, bh1);
            }
        }
    }

    // ---- C frags -> smem (stride 33 f32), then per-row epilogue ----
    __syncthreads();
    float* co = reinterpret_cast<float*>(sm);
    {
        const int r_c = lane >> 2;
        const int j2  = (lane & 3) * 2;
#pragma unroll
        for (int t = 0; t < 4; t++) {
            float* p0 = co + (m0 + r_c) * 33 + t * 8 + j2;
            float* p1 = co + (m0 + r_c + 8) * 33 + t * 8 + j2;
            p0[0] = C[t][0]; p0[1] = C[t][1];
            p1[0] = C[t][2]; p1[1] = C[t][3];
        }
    }
    __syncthreads();

    if (tid < 128) {
        const float* src = co + tid * 33;
        float o[30];
#pragma unroll
        for (int j = 0; j < 30; j++) o[j] = src[j];

        const int grow = row0 + tid;
        const int b = grow >> 11, n = grow & (Nn - 1);
        const float rs = 0.4472135954999579f;   // 1/sqrt(5)

        float q[10], kk[10], vv[10];
#pragma unroll
        for (int j = 0; j < 10; j++) {
            q[j]  = (o[j]      + bq[j]) * rs;
            kk[j] = (o[j + 10] + bk[j]);
            vv[j] = (o[j + 20] + bv[j]);
        }
#pragma unroll
        for (int h = 0; h < 2; h++) {
            int bh = b * NH + h;
            float* qp = g_Q[bh][n];
            float* kp = g_K[bh][n];
            float* vp = g_V[bh][n];
            *reinterpret_cast<float4*>(qp) = make_float4(q[h*5+0], q[h*5+1], q[h*5+2], q[h*5+3]);
            qp[4] = q[h*5+4];
            *reinterpret_cast<float4*>(kp) = make_float4(kk[h*5+0], kk[h*5+1], kk[h*5+2], kk[h*5+3]);
            kp[4] = kk[h*5+4];
            *reinterpret_cast<float4*>(vp) = make_float4(vv[h*5+0], vv[h*5+1], vv[h*5+2], vv[h*5+3]);
            vp[4] = vv[h*5+4];
        }
    }
}

// =====================================================================
// Kernel 2: causal attention (unchanged R7 winner): 4 queries/thread,
// KZ=8 key-split, transposed smem K/V, exp(sin(.)) with no running max.
// =====================================================================
#define TK 128

template <int CASE>
__device__ __forceinline__ void attn_tile4(
    const float* __restrict__ sK, const float* __restrict__ sV,
    const ull q2[4][5], int lim, ull acc[4][5], ull den[4])
{
    const ull* K2 = reinterpret_cast<const ull*>(sK);
    const ull* V2 = reinterpret_cast<const ull*>(sV);
#pragma unroll 4
    for (int p = 0; p < TK / 2; p++) {
        ull k0 = K2[p], k1 = K2[64 + p], k2 = K2[128 + p],
            k3 = K2[192 + p], k4 = K2[256 + p];
        ull v0 = V2[p], v1 = V2[64 + p], v2 = V2[128 + p],
            v3 = V2[192 + p], v4 = V2[256 + p];
#pragma unroll
        for (int i = 0; i < 4; i++) {
            const int mode = (CASE == 0) ? 0
                            : (i == CASE - 1) ? 1
                            : (i <  CASE - 1) ? 2 : 0;
            if (mode != 2) {
                ull s2 = mul2(q2[i][4], k4);
                fma2(s2, q2[i][0], k0);
                fma2(s2, q2[i][1], k1);
                fma2(s2, q2[i][2], k2);
                fma2(s2, q2[i][3], k3);
                float s0, s1; unpack2(s2, s0, s1);
                float e0 = __expf(__sinf(s0));
                float e1 = __expf(__sinf(s1));
                if (mode == 1) {
                    e0 = (2 * p     <= lim) ? e0 : 0.f;
                    e1 = (2 * p + 1 <= lim) ? e1 : 0.f;
                }
                ull e2 = pack2(e0, e1);
                add2(den[i], e2);
                fma2(acc[i][0], e2, v0);
                fma2(acc[i][1], e2, v1);
                fma2(acc[i][2], e2, v2);
                fma2(acc[i][3], e2, v3);
                fma2(acc[i][4], e2, v4);
            }
        }
    }
}

__global__ __launch_bounds__(128) void attn_kernel()
{
    __shared__ __align__(16) float sK[5 * TK];
    __shared__ __align__(16) float sV[5 * TK];

    const int tid = threadIdx.x;
    const int g   = (gridDim.x - 1) - blockIdx.x;
    const int bh  = blockIdx.y;
    const int kz  = blockIdx.z;

    const int ntiles = 4 * g + 4;
    const int t0 = (ntiles * kz)       / KZ;
    const int t1 = (ntiles * (kz + 1)) / KZ;

    ull acc[4][5], den[4];
#pragma unroll
    for (int i = 0; i < 4; i++) {
        den[i] = 0ull;
#pragma unroll
        for (int d = 0; d < 5; d++) acc[i][d] = 0ull;
    }

    if (t0 < t1) {
        ull q2[4][5];
#pragma unroll
        for (int i = 0; i < 4; i++) {
            const float* qp = g_Q[bh][(4 * g + i) * TK + tid];
            float4 qv = *reinterpret_cast<const float4*>(qp);
            float  q4 = qp[4];
            q2[i][0] = pack2(qv.x, qv.x); q2[i][1] = pack2(qv.y, qv.y);
            q2[i][2] = pack2(qv.z, qv.z); q2[i][3] = pack2(qv.w, qv.w);
            q2[i][4] = pack2(q4, q4);
        }

        float4 ka, va; float k4, v4;
        {
            const int j = t0 * TK + tid;
            ka = *reinterpret_cast<const float4*>(g_K[bh][j]);
            k4 = g_K[bh][j][4];
            va = *reinterpret_cast<const float4*>(g_V[bh][j]);
            v4 = g_V[bh][j][4];
        }

        for (int kt = t0; kt < t1; kt++) {
            __syncthreads();
            sK[0 * TK + tid] = ka.x; sK[1 * TK + tid] = ka.y;
            sK[2 * TK + tid] = ka.z; sK[3 * TK + tid] = ka.w;
            sK[4 * TK + tid] = k4;
            sV[0 * TK + tid] = va.x; sV[1 * TK + tid] = va.y;
            sV[2 * TK + tid] = va.z; sV[3 * TK + tid] = va.w;
            sV[4 * TK + tid] = v4;
            __syncthreads();

            if (kt + 1 < t1) {
                const int j = (kt + 1) * TK + tid;
                ka = *reinterpret_cast<const float4*>(g_K[bh][j]);
                k4 = g_K[bh][j][4];
                va = *reinterpret_cast<const float4*>(g_V[bh][j]);
                v4 = g_V[bh][j][4];
            }

            const int cs = kt - 4 * g;
            if (cs < 0)       attn_tile4<0>(sK, sV, q2, tid, acc, den);
            else if (cs == 0) attn_tile4<1>(sK, sV, q2, tid, acc, den);
            else if (cs == 1) attn_tile4<2>(sK, sV, q2, tid, acc, den);
            else if (cs == 2) attn_tile4<3>(sK, sV, q2, tid, acc, den);
            else              attn_tile4<4>(sK, sV, q2, tid, acc, den);
        }
    }

#pragma unroll
    for (int i = 0; i < 4; i++) {
        float a[5], dn;
#pragma unroll
        for (int d = 0; d < 5; d++) {
            float lo, hi; unpack2(acc[i][d], lo, hi);
            a[d] = lo + hi;
        }
        { float dl, dh; unpack2(den[i], dl, dh); dn = dl + dh; }
        float* op = g_A[bh][(4 * g + i) * TK + tid][kz];
        *reinterpret_cast<float4*>(op) = make_float4(a[0], a[1], a[2], a[3]);
        op[4] = a[4];
        op[5] = dn;
    }
}

// =====================================================================
// Kernel 3: combine attention partials + MLP head (unchanged R7).
// =====================================================================
#define MR 64

__global__ __launch_bounds__(256) void mlp_kernel(
    const float* __restrict__ Wm1, const float* __restrict__ bm1,
    const float* __restrict__ Wm2, const float* __restrict__ bm2,
    float* __restrict__ out)
{
    __shared__ __align__(16) float w2s[HID * DOUT];
    __shared__ __align__(16) float h1s[MR * HID];
    __shared__ float cs[MR * DK];

    const int tid  = threadIdx.x;
    const int row0 = blockIdx.x * MR;

    for (int e = tid; e < HID * DOUT / 4; e += 256)
        reinterpret_cast<float4*>(w2s)[e] = reinterpret_cast<const float4*>(Wm2)[e];

    for (int e = tid; e < MR * DK; e += 256) {
        int r = e / DK, k = e % DK;
        int h = k / DH, d = k % DH;
        int grow = row0 + r;
        int b = grow >> 11, n = grow & (Nn - 1);
        const float* A = g_A[b * NH + h][n][0];
        float den = 0.f, num = 0.f;
#pragma unroll
        for (int s = 0; s < KZ; s++) {
            num += A[8 * s + d];
            den += A[8 * s + 5];
        }
        cs[e] = num * __fdividef(1.f, den);
    }
    __syncthreads();

    for (int e = tid; e < MR * HID; e += 256) {
        int r = e / HID, j = e % HID;
        const float* crow = cs + r * DK;
        float s = bm1[j];
#pragma unroll
        for (int k = 0; k < DK; k++)
            s = fmaf(crow[k], Wm1[k * HID + j], s);
        h1s[e] = (s > 0.f) ? s : 0.01f * s;
    }
    __syncthreads();

    const int r  = tid >> 2;
    const int cg = tid & 3;
    ull h2[HID];
#pragma unroll
    for (int k = 0; k < HID; k++) {
        float hk = h1s[r * HID + k];
        h2[k] = pack2(hk, hk);
    }

    float* orow = out + (size_t)(row0 + r) * DOUT;
#pragma unroll 2
    for (int c4 = cg; c4 < DOUT / 4; c4 += 4) {
        union { float4 f; ull u[2]; } a;
        a.f = reinterpret_cast<const float4*>(bm2)[c4];
#pragma unroll
        for (int k = 0; k < HID; k++) {
            union { float4 f; ull u[2]; } w;
            w.f = *reinterpret_cast<const float4*>(w2s + k * DOUT + c4 * 4);
            fma2(a.u[0], h2[k], w.u[0]);
            fma2(a.u[1], h2[k], w.u[1]);
        }
        reinterpret_cast<float4*>(orow)[c4] = a.f;
    }
}

// =====================================================================
extern "C" void kernel_launch(void* const* d_in, const int* in_sizes, int n_in,
                              void* d_out, int out_size)
{
    const float* x   = (const float*)d_in[0];
    const float* Wq  = (const float*)d_in[1];
    const float* bq  = (const float*)d_in[2];
    const float* Wk  = (const float*)d_in[3];
    const float* bk  = (const float*)d_in[4];
    const float* Wv  = (const float*)d_in[5];
    const float* bv  = (const float*)d_in[6];
    const float* Wm1 = (const float*)d_in[7];
    const float* bm1 = (const float*)d_in[8];
    const float* Wm2 = (const float*)d_in[9];
    const float* bm2 = (const float*)d_in[10];

    proj_tc<<<ROWS / 128, 256>>>(x, Wq, bq, Wk, bk, Wv, bv);
    attn_kernel<<<dim3(Nn / TK / 4, 32, KZ), 128>>>();
    mlp_kernel<<<ROWS / MR, 256>>>(Wm1, bm1, Wm2, bm2, (float*)d_out);
}

// round 10
// speedup vs baseline: 1.6921x; 1.0921x over previous
#include <cuda_runtime.h>
#include <cuda_bf16.h>
#include <cstdint>

typedef unsigned long long ull;

// ---------------- packed f32x2 helpers (mlp) ----------------
__device__ __forceinline__ ull pack2(float lo, float hi) {
    ull r; asm("mov.b64 %0, {%1, %2};" : "=l"(r) : "f"(lo), "f"(hi)); return r;
}
__device__ __forceinline__ void fma2(ull& d, ull a, ull b) {
    asm("fma.rn.f32x2 %0, %1, %2, %0;" : "+l"(d) : "l"(a), "l"(b));
}

// ---------------- HMMA / misc helpers (family-portable: sm_80+) ----------------
__device__ __forceinline__ uint32_t smem_u32(const void* p) {
    uint32_t a;
    asm("{ .reg .u64 t; cvta.to.shared.u64 t, %1; cvt.u32.u64 %0, t; }" : "=r"(a) : "l"(p));
    return a;
}
__device__ __forceinline__ void ldsm4(uint32_t r[4], uint32_t addr) {
    asm volatile("ldmatrix.sync.aligned.m8n8.x4.shared.b16 {%0,%1,%2,%3}, [%4];"
        : "=r"(r[0]), "=r"(r[1]), "=r"(r[2]), "=r"(r[3]) : "r"(addr));
}
__device__ __forceinline__ void mma_k16(float c[4], const uint32_t a[4], uint32_t b0, uint32_t b1) {
    asm volatile("mma.sync.aligned.m16n8k16.row.col.f32.bf16.bf16.f32 "
        "{%0,%1,%2,%3}, {%4,%5,%6,%7}, {%8,%9}, {%0,%1,%2,%3};"
        : "+f"(c[0]), "+f"(c[1]), "+f"(c[2]), "+f"(c[3])
        : "r"(a[0]), "r"(a[1]), "r"(a[2]), "r"(a[3]), "r"(b0), "r"(b1));
}
__device__ __forceinline__ void mma_k8(float c[4], uint32_t a0, uint32_t a1, uint32_t b0) {
    asm volatile("mma.sync.aligned.m16n8k8.row.col.f32.bf16.bf16.f32 "
        "{%0,%1,%2,%3}, {%4,%5}, {%6}, {%0,%1,%2,%3};"
        : "+f"(c[0]), "+f"(c[1]), "+f"(c[2]), "+f"(c[3])
        : "r"(a0), "r"(a1), "r"(b0));
}
__device__ __forceinline__ uint32_t pbf2(float lo, float hi) {   // low half = lo
    uint32_t r; asm("cvt.rn.bf16x2.f32 %0, %1, %2;" : "=r"(r) : "f"(hi), "f"(lo)); return r;
}
__device__ __forceinline__ unsigned short bf16rn(float f) {
    unsigned short u; asm("cvt.rn.bf16.f32 %0, %1;" : "=h"(u) : "f"(f)); return u;
}
__device__ __forceinline__ float sin_ap(float x) {
    float r; asm("sin.approx.f32 %0, %1;" : "=f"(r) : "f"(x)); return r;
}
__device__ __forceinline__ float ex2_ap(float x) {
    float r; asm("ex2.approx.f32 %0, %1;" : "=f"(r) : "f"(x)); return r;
}

// ---------------- problem constants ----------------
#define Bn   16
#define Nn   2048
#define DIN  512
#define DK   10
#define NH   2
#define DH   5
#define HID  20
#define DOUT 512
#define ROWS (Bn * Nn)             // 32768
#define KZ   8

// ---------------- device scratch (padding dims 5..7 stay zero-init) ----------------
__device__ float g_Q[32][Nn][8];       // Q pre-scaled by 1/sqrt(5)
__device__ float g_K[32][Nn][8];
__device__ float g_V[32][Nn][8];
__device__ float g_A[32][Nn][KZ][8];

// =====================================================================
// Kernel 1: QKV projection on HMMA (unchanged R9 winner).
// =====================================================================
#define XSTR 72
#define XH_OFF 0
#define XL_OFF (128 * XSTR * 2)
#define WH_OFF (2 * 128 * XSTR * 2)
#define WL_OFF (WH_OFF + 32 * XSTR * 2)
#define SM_TOT (WL_OFF + 32 * XSTR * 2)

__global__ __launch_bounds__(256) void proj_tc(
    const float* __restrict__ x,
    const float* __restrict__ Wq, const float* __restrict__ bq,
    const float* __restrict__ Wk, const float* __restrict__ bk,
    const float* __restrict__ Wv, const float* __restrict__ bv)
{
    __shared__ __align__(16) char sm[SM_TOT];
    const uint32_t sb = smem_u32(sm);

    const int tid  = threadIdx.x;
    const int wid  = tid >> 5;
    const int lane = tid & 31;
    const int row0 = blockIdx.x * 128;
    const int m0   = wid * 16;

    float C[4][4];
#pragma unroll
    for (int t = 0; t < 4; t++)
#pragma unroll
        for (int i = 0; i < 4; i++) C[t][i] = 0.f;

    float4 xr[8];
    float  wr[8];
#pragma unroll
    for (int it = 0; it < 8; it++) {
        int e = tid + it * 256;
        int r = e >> 4, c4 = e & 15;
        xr[it] = *reinterpret_cast<const float4*>(x + (size_t)(row0 + r) * DIN + c4 * 4);
    }
#pragma unroll
    for (int it = 0; it < 8; it++) {
        int e = tid + it * 256;
        int k = e >> 5, j = e & 31;
        wr[it] = (j < 10) ? Wq[k * DK + j]
               : (j < 20) ? Wk[k * DK + (j - 10)]
               : (j < 30) ? Wv[k * DK + (j - 20)] : 0.f;
    }

    const int arow = lane & 15;
    const int agrp = lane >> 4;
    const int bn = lane >> 2;
    const int bk0 = (lane & 3) * 2;

    for (int c = 0; c < 8; c++) {
        __syncthreads();
#pragma unroll
        for (int it = 0; it < 8; it++) {
            int e = tid + it * 256;
            int r = e >> 4, c4 = e & 15;
            float4 v = xr[it];
            uint32_t b0 = __float_as_uint(v.x), b1 = __float_as_uint(v.y);
            uint32_t b2 = __float_as_uint(v.z), b3 = __float_as_uint(v.w);
            uint32_t h01 = __byte_perm(b0, b1, 0x7632);
            uint32_t h23 = __byte_perm(b2, b3, 0x7632);
            float l0 = v.x - __uint_as_float(b0 & 0xFFFF0000u);
            float l1 = v.y - __uint_as_float(b1 & 0xFFFF0000u);
            float l2 = v.z - __uint_as_float(b2 & 0xFFFF0000u);
            float l3 = v.w - __uint_as_float(b3 & 0xFFFF0000u);
            uint32_t off = (r * XSTR + c4 * 4) * 2;
            *reinterpret_cast<uint2*>(sm + XH_OFF + off) = make_uint2(h01, h23);
            *reinterpret_cast<uint2*>(sm + XL_OFF + off) =
                make_uint2(pbf2(l0, l1), pbf2(l2, l3));
        }
#pragma unroll
        for (int it = 0; it < 8; it++) {
            int e = tid + it * 256;
            int k = e >> 5, j = e & 31;
            float w = wr[it];
            uint32_t wb = __float_as_uint(w);
            unsigned short whi = (unsigned short)(wb >> 16);
            unsigned short wlo = bf16rn(w - __uint_as_float(wb & 0xFFFF0000u));
            uint32_t off = (j * XSTR + k) * 2;
            *reinterpret_cast<unsigned short*>(sm + WH_OFF + off) = whi;
            *reinterpret_cast<unsigned short*>(sm + WL_OFF + off) = wlo;
        }
        __syncthreads();

        if (c < 7) {
            const int kc = (c + 1) * 64;
#pragma unroll
            for (int it = 0; it < 8; it++) {
                int e = tid + it * 256;
                int r = e >> 4, c4 = e & 15;
                xr[it] = *reinterpret_cast<const float4*>(
                    x + (size_t)(row0 + r) * DIN + kc + c4 * 4);
            }
#pragma unroll
            for (int it = 0; it < 8; it++) {
                int e = tid + it * 256;
                int k = kc + (e >> 5), j = e & 31;
                wr[it] = (j < 10) ? Wq[k * DK + j]
                       : (j < 20) ? Wk[k * DK + (j - 10)]
                       : (j < 30) ? Wv[k * DK + (j - 20)] : 0.f;
            }
        }

#pragma unroll
        for (int ks = 0; ks < 4; ks++) {
            uint32_t ah[4], al[4];
            uint32_t abase = (m0 + arow) * (XSTR * 2) + ks * 32 + agrp * 16;
            ldsm4(ah, sb + XH_OFF + abase);
            ldsm4(al, sb + XL_OFF + abase);
#pragma unroll
            for (int t = 0; t < 4; t++) {
                uint32_t boff = ((bn + t * 8) * XSTR + ks * 16 + bk0) * 2;
                uint32_t bh0 = *reinterpret_cast<const uint32_t*>(sm + WH_OFF + boff);
                uint32_t bh1 = *reinterpret_cast<const uint32_t*>(sm + WH_OFF + boff + 16);
                uint32_t bl0 = *reinterpret_cast<const uint32_t*>(sm + WL_OFF + boff);
                uint32_t bl1 = *reinterpret_cast<const uint32_t*>(sm + WL_OFF + boff + 16);
                mma_k16(C[t], ah, bh0, bh1);
                mma_k16(C[t], ah, bl0, bl1);
                mma_k16(C[t], al, bh0, bh1);
            }
        }
    }

    __syncthreads();
    float* co = reinterpret_cast<float*>(sm);
    {
        const int r_c = lane >> 2;
        const int j2  = (lane & 3) * 2;
#pragma unroll
        for (int t = 0; t < 4; t++) {
            float* p0 = co + (m0 + r_c) * 33 + t * 8 + j2;
            float* p1 = co + (m0 + r_c + 8) * 33 + t * 8 + j2;
            p0[0] = C[t][0]; p0[1] = C[t][1];
            p1[0] = C[t][2]; p1[1] = C[t][3];
        }
    }
    __syncthreads();

    if (tid < 128) {
        const float* src = co + tid * 33;
        float o[30];
#pragma unroll
        for (int j = 0; j < 30; j++) o[j] = src[j];

        const int grow = row0 + tid;
        const int b = grow >> 11, n = grow & (Nn - 1);
        const float rs = 0.4472135954999579f;

        float q[10], kk[10], vv[10];
#pragma unroll
        for (int j = 0; j < 10; j++) {
            q[j]  = (o[j]      + bq[j]) * rs;
            kk[j] = (o[j + 10] + bk[j]);
            vv[j] = (o[j + 20] + bv[j]);
        }
#pragma unroll
        for (int h = 0; h < 2; h++) {
            int bh = b * NH + h;
            float* qp = g_Q[bh][n];
            float* kp = g_K[bh][n];
            float* vp = g_V[bh][n];
            *reinterpret_cast<float4*>(qp) = make_float4(q[h*5+0], q[h*5+1], q[h*5+2], q[h*5+3]);
            qp[4] = q[h*5+4];
            *reinterpret_cast<float4*>(kp) = make_float4(kk[h*5+0], kk[h*5+1], kk[h*5+2], kk[h*5+3]);
            kp[4] = kk[h*5+4];
            *reinterpret_cast<float4*>(vp) = make_float4(vv[h*5+0], vv[h*5+1], vv[h*5+2], vv[h*5+3]);
            vp[4] = vv[h*5+4];
        }
    }
}

// =====================================================================
// Kernel 2: HMMA attention. Block = 8 warps x 16 queries = 128 queries.
// S = Q·K^T via mma.m16n8k8 split-bf16; P = ex2(sin(S)*log2e) elementwise
// in C-fragments; P packs directly into PV A-frags (layout identity).
// PV via mma.m16n8k16 with V transposed + ones-column at dim 5 -> one mma
// yields both sum(p*v) and sum(p). Split-bf16 on P and V.
// Keys chunked 128 into smem; KZ=8 partial split; causal mask in-fragment
// on the diagonal chunk only; sub-tiles past the diagonal skipped.
// =====================================================================
#define AQH 0
#define AQL 2048
#define AKH 4096
#define AKL 6144
#define AVH 8192
#define AVL (AVH + 8 * 136 * 2)       // 10368
#define AT_SM (AVL + 8 * 136 * 2)     // 12544

__global__ __launch_bounds__(256) void attn_tc()
{
    __shared__ __align__(16) char sm[AT_SM];
    const uint32_t sb = smem_u32(sm);

    const int tid  = threadIdx.x;
    const int wid  = tid >> 5;
    const int lane = tid & 31;
    const int qt   = (Nn / 128 - 1) - blockIdx.x;    // heavy tiles first
    const int bh   = blockIdx.y;
    const int kz   = blockIdx.z;
    const int m0   = wid * 16;
    const int r    = lane >> 2;
    const int j    = lane & 3;

    const int nt = qt + 1;                            // 128-key chunks
    const int t0 = (nt * kz) / KZ, t1 = (nt * (kz + 1)) / KZ;

    // zero Vt padding rows 6,7 (read as B-frag n=6,7)
    for (int e = tid; e < 136; e += 256) {
        *reinterpret_cast<uint32_t*>(sm + AVH + (6 * 136) * 2 + e * 4) = 0;
        *reinterpret_cast<uint32_t*>(sm + AVL + (6 * 136) * 2 + e * 4) = 0;
    }

    // ---- stage Q hi/lo bf16 [128][8] ----
    if (tid < 128) {
        const float* qp = g_Q[bh][qt * 128 + tid];
        float4 v0 = *reinterpret_cast<const float4*>(qp);
        float  q4 = qp[4];
        float v[8] = {v0.x, v0.y, v0.z, v0.w, q4, 0.f, 0.f, 0.f};
        uint32_t hb[4]; uint32_t lb[4];
#pragma unroll
        for (int i = 0; i < 4; i++) {
            uint32_t b0 = __float_as_uint(v[2*i]), b1 = __float_as_uint(v[2*i+1]);
            hb[i] = __byte_perm(b0, b1, 0x7632);
            float l0 = v[2*i]   - __uint_as_float(b0 & 0xFFFF0000u);
            float l1 = v[2*i+1] - __uint_as_float(b1 & 0xFFFF0000u);
            lb[i] = pbf2(l0, l1);
        }
        *reinterpret_cast<uint4*>(sm + AQH + tid * 16) = make_uint4(hb[0], hb[1], hb[2], hb[3]);
        *reinterpret_cast<uint4*>(sm + AQL + tid * 16) = make_uint4(lb[0], lb[1], lb[2], lb[3]);
    }
    __syncthreads();

    // Q A-frags (k8): rows m0+r, m0+r+8; dim pair j
    uint32_t qh0, qh1, ql0, ql1;
    {
        uint32_t w0 = (m0 + r) * 16 + j * 4;
        uint32_t w1 = (m0 + r + 8) * 16 + j * 4;
        qh0 = *reinterpret_cast<const uint32_t*>(sm + AQH + w0);
        qh1 = *reinterpret_cast<const uint32_t*>(sm + AQH + w1);
        ql0 = *reinterpret_cast<const uint32_t*>(sm + AQL + w0);
        ql1 = *reinterpret_cast<const uint32_t*>(sm + AQL + w1);
    }

    float Cpv[4] = {0.f, 0.f, 0.f, 0.f};

    // prefetch first chunk rows (fp32): tid<128 -> V row, else K row
    float4 pA, pB;
    if (t0 < t1) {
        int key = t0 * 128 + (tid & 127);
        const float* p = (tid < 128) ? g_V[bh][key] : g_K[bh][key];
        pA = *reinterpret_cast<const float4*>(p);
        pB = *reinterpret_cast<const float4*>(p + 4);
    }

    const float LOG2E = 1.4426950408889634f;

    for (int ck = t0; ck < t1; ck++) {
        __syncthreads();
        if (tid < 128) {
            // V: transposed store [dim][136], dim5 = ones
            float v[8] = {pA.x, pA.y, pA.z, pA.w, pB.x, 1.0f, 0.f, 0.f};
            int key = tid;
#pragma unroll
            for (int d = 0; d < 6; d++) {
                uint32_t b = __float_as_uint(v[d]);
                unsigned short h = (unsigned short)(b >> 16);
                unsigned short l = bf16rn(v[d] - __uint_as_float(b & 0xFFFF0000u));
                *reinterpret_cast<unsigned short*>(sm + AVH + (d * 136 + key) * 2) = h;
                *reinterpret_cast<unsigned short*>(sm + AVL + (d * 136 + key) * 2) = l;
            }
        } else {
            // K: row store [key][8]
            float v[8] = {pA.x, pA.y, pA.z, pA.w, pB.x, 0.f, 0.f, 0.f};
            uint32_t hb[4], lb[4];
#pragma unroll
            for (int i = 0; i < 4; i++) {
                uint32_t b0 = __float_as_uint(v[2*i]), b1 = __float_as_uint(v[2*i+1]);
                hb[i] = __byte_perm(b0, b1, 0x7632);
                float l0 = v[2*i]   - __uint_as_float(b0 & 0xFFFF0000u);
                float l1 = v[2*i+1] - __uint_as_float(b1 & 0xFFFF0000u);
                lb[i] = pbf2(l0, l1);
            }
            int key = tid - 128;
            *reinterpret_cast<uint4*>(sm + AKH + key * 16) = make_uint4(hb[0], hb[1], hb[2], hb[3]);
            *reinterpret_cast<uint4*>(sm + AKL + key * 16) = make_uint4(lb[0], lb[1], lb[2], lb[3]);
        }
        __syncthreads();

        if (ck + 1 < t1) {
            int key = (ck + 1) * 128 + (tid & 127);
            const float* p = (tid < 128) ? g_V[bh][key] : g_K[bh][key];
            pA = *reinterpret_cast<const float4*>(p);
            pB = *reinterpret_cast<const float4*>(p + 4);
        }

        const bool diag = (ck == qt);

#pragma unroll 2
        for (int ks = 0; ks < 8; ks++) {
            const int kbase = ks * 16;
            if (diag && kbase > m0 + 15) break;          // fully past diagonal
            const bool needMask = diag && (kbase + 15 > m0);

            // ---- S = Q K^T (two n8 groups, split bf16) ----
            float c0[4] = {0.f,0.f,0.f,0.f}, c1[4] = {0.f,0.f,0.f,0.f};
            {
                uint32_t o0 = (kbase + r) * 16 + j * 4;
                uint32_t o1 = (kbase + 8 + r) * 16 + j * 4;
                uint32_t b0h = *reinterpret_cast<const uint32_t*>(sm + AKH + o0);
                uint32_t b0l = *reinterpret_cast<const uint32_t*>(sm + AKL + o0);
                uint32_t b1h = *reinterpret_cast<const uint32_t*>(sm + AKH + o1);
                uint32_t b1l = *reinterpret_cast<const uint32_t*>(sm + AKL + o1);
                mma_k8(c0, qh0, qh1, b0h);
                mma_k8(c0, qh0, qh1, b0l);
                mma_k8(c0, ql0, ql1, b0h);
                mma_k8(c1, qh0, qh1, b1h);
                mma_k8(c1, qh0, qh1, b1l);
                mma_k8(c1, ql0, ql1, b1h);
            }

            // ---- P = exp(sin(S)) elementwise ----
            float p[8];
#pragma unroll
            for (int i = 0; i < 4; i++) p[i]     = ex2_ap(sin_ap(c0[i]) * LOG2E);
#pragma unroll
            for (int i = 0; i < 4; i++) p[4 + i] = ex2_ap(sin_ap(c1[i]) * LOG2E);

            if (needMask) {
                int q_lo = m0 + r, q_hi = q_lo + 8;
                int k00 = kbase + 2 * j, k01 = k00 + 1;
                int k10 = k00 + 8,       k11 = k01 + 8;
                p[0] = (k00 <= q_lo) ? p[0] : 0.f;
                p[1] = (k01 <= q_lo) ? p[1] : 0.f;
                p[2] = (k00 <= q_hi) ? p[2] : 0.f;
                p[3] = (k01 <= q_hi) ? p[3] : 0.f;
                p[4] = (k10 <= q_lo) ? p[4] : 0.f;
                p[5] = (k11 <= q_lo) ? p[5] : 0.f;
                p[6] = (k10 <= q_hi) ? p[6] : 0.f;
                p[7] = (k11 <= q_hi) ? p[7] : 0.f;
            }

            // ---- pack P into PV A-frags (hi + lo) ----
            uint32_t ah[4], al[4];
#pragma unroll
            for (int i = 0; i < 4; i++) {
                uint32_t h = pbf2(p[2*i], p[2*i+1]);
                ah[i] = h;
                float r0 = __uint_as_float(h << 16);
                float r1 = __uint_as_float(h & 0xFFFF0000u);
                al[i] = pbf2(p[2*i] - r0, p[2*i+1] - r1);
            }

            // ---- V B-frags (k16, n = dim incl. ones col) ----
            uint32_t vo = (r * 136 + kbase + 2 * j) * 2;
            uint32_t bvh0 = *reinterpret_cast<const uint32_t*>(sm + AVH + vo);
            uint32_t bvh1 = *reinterpret_cast<const uint32_t*>(sm + AVH + vo + 16);
            uint32_t bvl0 = *reinterpret_cast<const uint32_t*>(sm + AVL + vo);
            uint32_t bvl1 = *reinterpret_cast<const uint32_t*>(sm + AVL + vo + 16);

            mma_k16(Cpv, ah, bvh0, bvh1);
            mma_k16(Cpv, ah, bvl0, bvl1);
            mma_k16(Cpv, al, bvh0, bvh1);
        }
    }

    // ---- write partials: cols 0..4 = sum(p*v), col 5 = sum(p) ----
    if (j < 3) {
        int q1 = qt * 128 + m0 + r;
        *reinterpret_cast<float2*>(&g_A[bh][q1][kz][2 * j]) = make_float2(Cpv[0], Cpv[1]);
        int q2 = q1 + 8;
        *reinterpret_cast<float2*>(&g_A[bh][q2][kz][2 * j]) = make_float2(Cpv[2], Cpv[3]);
    }
}

// =====================================================================
// Kernel 3: combine attention partials + MLP head (unchanged).
// =====================================================================
#define MR 64

__global__ __launch_bounds__(256) void mlp_kernel(
    const float* __restrict__ Wm1, const float* __restrict__ bm1,
    const float* __restrict__ Wm2, const float* __restrict__ bm2,
    float* __restrict__ out)
{
    __shared__ __align__(16) float w2s[HID * DOUT];
    __shared__ __align__(16) float h1s[MR * HID];
    __shared__ float cs[MR * DK];

    const int tid  = threadIdx.x;
    const int row0 = blockIdx.x * MR;

    for (int e = tid; e < HID * DOUT / 4; e += 256)
        reinterpret_cast<float4*>(w2s)[e] = reinterpret_cast<const float4*>(Wm2)[e];

    for (int e = tid; e < MR * DK; e += 256) {
        int r = e / DK, k = e % DK;
        int h = k / DH, d = k % DH;
        int grow = row0 + r;
        int b = grow >> 11, n = grow & (Nn - 1);
        const float* A = g_A[b * NH + h][n][0];
        float den = 0.f, num = 0.f;
#pragma unroll
        for (int s = 0; s < KZ; s++) {
            num += A[8 * s + d];
            den += A[8 * s + 5];
        }
        cs[e] = num * __fdividef(1.f, den);
    }
    __syncthreads();

    for (int e = tid; e < MR * HID; e += 256) {
        int r = e / HID, j = e % HID;
        const float* crow = cs + r * DK;
        float s = bm1[j];
#pragma unroll
        for (int k = 0; k < DK; k++)
            s = fmaf(crow[k], Wm1[k * HID + j], s);
        h1s[e] = (s > 0.f) ? s : 0.01f * s;
    }
    __syncthreads();

    const int r  = tid >> 2;
    const int cg = tid & 3;
    ull h2[HID];
#pragma unroll
    for (int k = 0; k < HID; k++) {
        float hk = h1s[r * HID + k];
        h2[k] = pack2(hk, hk);
    }

    float* orow = out + (size_t)(row0 + r) * DOUT;
#pragma unroll 2
    for (int c4 = cg; c4 < DOUT / 4; c4 += 4) {
        union { float4 f; ull u[2]; } a;
        a.f = reinterpret_cast<const float4*>(bm2)[c4];
#pragma unroll
        for (int k = 0; k < HID; k++) {
            union { float4 f; ull u[2]; } w;
            w.f = *reinterpret_cast<const float4*>(w2s + k * DOUT + c4 * 4);
            fma2(a.u[0], h2[k], w.u[0]);
            fma2(a.u[1], h2[k], w.u[1]);
        }
        reinterpret_cast<float4*>(orow)[c4] = a.f;
    }
}

// =====================================================================
extern "C" void kernel_launch(void* const* d_in, const int* in_sizes, int n_in,
                              void* d_out, int out_size)
{
    const float* x   = (const float*)d_in[0];
    const float* Wq  = (const float*)d_in[1];
    const float* bq  = (const float*)d_in[2];
    const float* Wk  = (const float*)d_in[3];
    const float* bk  = (const float*)d_in[4];
    const float* Wv  = (const float*)d_in[5];
    const float* bv  = (const float*)d_in[6];
    const float* Wm1 = (const float*)d_in[7];
    const float* bm1 = (const float*)d_in[8];
    const float* Wm2 = (const float*)d_in[9];
    const float* bm2 = (const float*)d_in[10];

    proj_tc<<<ROWS / 128, 256>>>(x, Wq, bq, Wk, bk, Wv, bv);
    attn_tc<<<dim3(Nn / 128, 32, KZ), 256>>>();
    mlp_kernel<<<ROWS / MR, 256>>>(Wm1, bm1, Wm2, bm2, (float*)d_out);
}

// round 11
// speedup vs baseline: 2.0759x; 1.2268x over previous
#include <cuda_runtime.h>
#include <cuda_bf16.h>
#include <cstdint>

typedef unsigned long long ull;

// ---------------- HMMA / misc helpers (family-portable: sm_80+) ----------------
__device__ __forceinline__ uint32_t smem_u32(const void* p) {
    uint32_t a;
    asm("{ .reg .u64 t; cvta.to.shared.u64 t, %1; cvt.u32.u64 %0, t; }" : "=r"(a) : "l"(p));
    return a;
}
__device__ __forceinline__ void ldsm4(uint32_t r[4], uint32_t addr) {
    asm volatile("ldmatrix.sync.aligned.m8n8.x4.shared.b16 {%0,%1,%2,%3}, [%4];"
        : "=r"(r[0]), "=r"(r[1]), "=r"(r[2]), "=r"(r[3]) : "r"(addr));
}
__device__ __forceinline__ void mma_k16(float c[4], const uint32_t a[4], uint32_t b0, uint32_t b1) {
    asm volatile("mma.sync.aligned.m16n8k16.row.col.f32.bf16.bf16.f32 "
        "{%0,%1,%2,%3}, {%4,%5,%6,%7}, {%8,%9}, {%0,%1,%2,%3};"
        : "+f"(c[0]), "+f"(c[1]), "+f"(c[2]), "+f"(c[3])
        : "r"(a[0]), "r"(a[1]), "r"(a[2]), "r"(a[3]), "r"(b0), "r"(b1));
}
__device__ __forceinline__ void mma_k8(float c[4], uint32_t a0, uint32_t a1, uint32_t b0) {
    asm volatile("mma.sync.aligned.m16n8k8.row.col.f32.bf16.bf16.f32 "
        "{%0,%1,%2,%3}, {%4,%5}, {%6}, {%0,%1,%2,%3};"
        : "+f"(c[0]), "+f"(c[1]), "+f"(c[2]), "+f"(c[3])
        : "r"(a0), "r"(a1), "r"(b0));
}
__device__ __forceinline__ uint32_t pbf2(float lo, float hi) {   // low half = lo
    uint32_t r; asm("cvt.rn.bf16x2.f32 %0, %1, %2;" : "=r"(r) : "f"(hi), "f"(lo)); return r;
}
__device__ __forceinline__ unsigned short bf16rn(float f) {
    unsigned short u; asm("cvt.rn.bf16.f32 %0, %1;" : "=h"(u) : "f"(f)); return u;
}
__device__ __forceinline__ float sin_ap(float x) {
    float r; asm("sin.approx.f32 %0, %1;" : "=f"(r) : "f"(x)); return r;
}
__device__ __forceinline__ float ex2_ap(float x) {
    float r; asm("ex2.approx.f32 %0, %1;" : "=f"(r) : "f"(x)); return r;
}
// split pair of fp32 into packed bf16 hi (truncation) + lo (residual)
__device__ __forceinline__ void split2(float a, float b, uint32_t& h, uint32_t& l) {
    uint32_t ba = __float_as_uint(a), bb = __float_as_uint(b);
    h = __byte_perm(ba, bb, 0x7632);
    l = pbf2(a - __uint_as_float(ba & 0xFFFF0000u),
             b - __uint_as_float(bb & 0xFFFF0000u));
}

// ---------------- problem constants ----------------
#define Bn   16
#define Nn   2048
#define DIN  512
#define DK   10
#define NH   2
#define DH   5
#define HID  20
#define DOUT 512
#define ROWS (Bn * Nn)             // 32768
#define KZ   4

// ---------------- device scratch ----------------
// Q/K packed split-bf16: [0..3]=hi pairs (d0d1,d2d3,d4·0,0), [4..7]=lo pairs
__device__ uint32_t g_Qb[32][Nn][8];
__device__ uint32_t g_Kb[32][Nn][8];
// V transposed split-bf16: [dim 0..4][n]
__device__ unsigned short g_Vth[32][5][Nn];
__device__ unsigned short g_Vtl[32][5][Nn];
// attention partials: [bh][q][kz][ a0..a4, den, pad, pad ]
__device__ float g_A[32][Nn][KZ][8];

// =====================================================================
// Kernel 1: QKV projection on HMMA (R9 core; epilogue emits split-bf16).
// =====================================================================
#define XSTR 72
#define XH_OFF 0
#define XL_OFF (128 * XSTR * 2)
#define WH_OFF (2 * 128 * XSTR * 2)
#define WL_OFF (WH_OFF + 32 * XSTR * 2)
#define SM_TOT (WL_OFF + 32 * XSTR * 2)

__global__ __launch_bounds__(256) void proj_tc(
    const float* __restrict__ x,
    const float* __restrict__ Wq, const float* __restrict__ bq,
    const float* __restrict__ Wk, const float* __restrict__ bk,
    const float* __restrict__ Wv, const float* __restrict__ bv)
{
    __shared__ __align__(16) char sm[SM_TOT];
    const uint32_t sb = smem_u32(sm);

    const int tid  = threadIdx.x;
    const int wid  = tid >> 5;
    const int lane = tid & 31;
    const int row0 = blockIdx.x * 128;
    const int m0   = wid * 16;

    float C[4][4];
#pragma unroll
    for (int t = 0; t < 4; t++)
#pragma unroll
        for (int i = 0; i < 4; i++) C[t][i] = 0.f;

    float4 xr[8];
    float  wr[8];
#pragma unroll
    for (int it = 0; it < 8; it++) {
        int e = tid + it * 256;
        int r = e >> 4, c4 = e & 15;
        xr[it] = *reinterpret_cast<const float4*>(x + (size_t)(row0 + r) * DIN + c4 * 4);
    }
#pragma unroll
    for (int it = 0; it < 8; it++) {
        int e = tid + it * 256;
        int k = e >> 5, j = e & 31;
        wr[it] = (j < 10) ? Wq[k * DK + j]
               : (j < 20) ? Wk[k * DK + (j - 10)]
               : (j < 30) ? Wv[k * DK + (j - 20)] : 0.f;
    }

    const int arow = lane & 15;
    const int agrp = lane >> 4;
    const int bn = lane >> 2;
    const int bk0 = (lane & 3) * 2;

    for (int c = 0; c < 8; c++) {
        __syncthreads();
#pragma unroll
        for (int it = 0; it < 8; it++) {
            int e = tid + it * 256;
            int r = e >> 4, c4 = e & 15;
            float4 v = xr[it];
            uint32_t h01, l01, h23, l23;
            split2(v.x, v.y, h01, l01);
            split2(v.z, v.w, h23, l23);
            uint32_t off = (r * XSTR + c4 * 4) * 2;
            *reinterpret_cast<uint2*>(sm + XH_OFF + off) = make_uint2(h01, h23);
            *reinterpret_cast<uint2*>(sm + XL_OFF + off) = make_uint2(l01, l23);
        }
#pragma unroll
        for (int it = 0; it < 8; it++) {
            int e = tid + it * 256;
            int k = e >> 5, j = e & 31;
            float w = wr[it];
            uint32_t wb = __float_as_uint(w);
            unsigned short whi = (unsigned short)(wb >> 16);
            unsigned short wlo = bf16rn(w - __uint_as_float(wb & 0xFFFF0000u));
            uint32_t off = (j * XSTR + k) * 2;
            *reinterpret_cast<unsigned short*>(sm + WH_OFF + off) = whi;
            *reinterpret_cast<unsigned short*>(sm + WL_OFF + off) = wlo;
        }
        __syncthreads();

        if (c < 7) {
            const int kc = (c + 1) * 64;
#pragma unroll
            for (int it = 0; it < 8; it++) {
                int e = tid + it * 256;
                int r = e >> 4, c4 = e & 15;
                xr[it] = *reinterpret_cast<const float4*>(
                    x + (size_t)(row0 + r) * DIN + kc + c4 * 4);
            }
#pragma unroll
            for (int it = 0; it < 8; it++) {
                int e = tid + it * 256;
                int k = kc + (e >> 5), j = e & 31;
                wr[it] = (j < 10) ? Wq[k * DK + j]
                       : (j < 20) ? Wk[k * DK + (j - 10)]
                       : (j < 30) ? Wv[k * DK + (j - 20)] : 0.f;
            }
        }

#pragma unroll
        for (int ks = 0; ks < 4; ks++) {
            uint32_t ah[4], al[4];
            uint32_t abase = (m0 + arow) * (XSTR * 2) + ks * 32 + agrp * 16;
            ldsm4(ah, sb + XH_OFF + abase);
            ldsm4(al, sb + XL_OFF + abase);
#pragma unroll
            for (int t = 0; t < 4; t++) {
                uint32_t boff = ((bn + t * 8) * XSTR + ks * 16 + bk0) * 2;
                uint32_t bh0 = *reinterpret_cast<const uint32_t*>(sm + WH_OFF + boff);
                uint32_t bh1 = *reinterpret_cast<const uint32_t*>(sm + WH_OFF + boff + 16);
                uint32_t bl0 = *reinterpret_cast<const uint32_t*>(sm + WL_OFF + boff);
                uint32_t bl1 = *reinterpret_cast<const uint32_t*>(sm + WL_OFF + boff + 16);
                mma_k16(C[t], ah, bh0, bh1);
                mma_k16(C[t], ah, bl0, bl1);
                mma_k16(C[t], al, bh0, bh1);
            }
        }
    }

    __syncthreads();
    float* co = reinterpret_cast<float*>(sm);
    {
        const int r_c = lane >> 2;
        const int j2  = (lane & 3) * 2;
#pragma unroll
        for (int t = 0; t < 4; t++) {
            float* p0 = co + (m0 + r_c) * 33 + t * 8 + j2;
            float* p1 = co + (m0 + r_c + 8) * 33 + t * 8 + j2;
            p0[0] = C[t][0]; p0[1] = C[t][1];
            p1[0] = C[t][2]; p1[1] = C[t][3];
        }
    }
    __syncthreads();

    if (tid < 128) {
        const float* src = co + tid * 33;
        float o[30];
#pragma unroll
        for (int j = 0; j < 30; j++) o[j] = src[j];

        const int grow = row0 + tid;
        const int b = grow >> 11, n = grow & (Nn - 1);
        const float rs = 0.4472135954999579f;   // 1/sqrt(5)

        float q[10], kk[10], vv[10];
#pragma unroll
        for (int j = 0; j < 10; j++) {
            q[j]  = (o[j]      + bq[j]) * rs;
            kk[j] = (o[j + 10] + bk[j]);
            vv[j] = (o[j + 20] + bv[j]);
        }
#pragma unroll
        for (int h = 0; h < 2; h++) {
            int bh = b * NH + h;
            uint32_t qh[4], ql[4], kh[4], kl[4];
            split2(q[h*5+0], q[h*5+1], qh[0], ql[0]);
            split2(q[h*5+2], q[h*5+3], qh[1], ql[1]);
            split2(q[h*5+4], 0.f,      qh[2], ql[2]);
            qh[3] = 0; ql[3] = 0;
            split2(kk[h*5+0], kk[h*5+1], kh[0], kl[0]);
            split2(kk[h*5+2], kk[h*5+3], kh[1], kl[1]);
            split2(kk[h*5+4], 0.f,       kh[2], kl[2]);
            kh[3] = 0; kl[3] = 0;
            *reinterpret_cast<uint4*>(&g_Qb[bh][n][0]) = make_uint4(qh[0], qh[1], qh[2], qh[3]);
            *reinterpret_cast<uint4*>(&g_Qb[bh][n][4]) = make_uint4(ql[0], ql[1], ql[2], ql[3]);
            *reinterpret_cast<uint4*>(&g_Kb[bh][n][0]) = make_uint4(kh[0], kh[1], kh[2], kh[3]);
            *reinterpret_cast<uint4*>(&g_Kb[bh][n][4]) = make_uint4(kl[0], kl[1], kl[2], kl[3]);
#pragma unroll
            for (int d = 0; d < 5; d++) {
                float v = vv[h*5+d];
                uint32_t vb = __float_as_uint(v);
                g_Vth[bh][d][n] = (unsigned short)(vb >> 16);
                g_Vtl[bh][d][n] = bf16rn(v - __uint_as_float(vb & 0xFFFF0000u));
            }
        }
    }
}

// =====================================================================
// Kernel 2: HMMA attention; all operands precomputed split-bf16 ->
// staging is pure copies. Block = 8 warps x 16 q = 128 queries.
// S via mma.m16n8k8; P = ex2(sin(S)*log2e) in-fragment; PV via
// mma.m16n8k16 with ones-column (row 5 of Vt, set once) -> sum(p).
// Keys chunked 128; KZ=4 partial split; diag mask in-fragment.
// =====================================================================
#define AQH 0
#define AQL 2048
#define AKH 4096
#define AKL 6144
#define AVH 8192
#define AVL (AVH + 8 * 136 * 2)       // 10368
#define AT_SM (AVL + 8 * 136 * 2)     // 12544

__global__ __launch_bounds__(256) void attn_tc()
{
    __shared__ __align__(16) char sm[AT_SM];

    const int tid  = threadIdx.x;
    const int wid  = tid >> 5;
    const int lane = tid & 31;
    const int qt   = (Nn / 128 - 1) - blockIdx.x;    // heavy tiles first
    const int bh   = blockIdx.y;
    const int kz   = blockIdx.z;
    const int m0   = wid * 16;
    const int r    = lane >> 2;
    const int j    = lane & 3;

    const int nt = qt + 1;
    const int t0 = (nt * kz) / KZ, t1 = (nt * (kz + 1)) / KZ;

    float Cpv[4] = {0.f, 0.f, 0.f, 0.f};
    const float LOG2E = 1.4426950408889634f;

    if (t0 < t1) {
        // ones row (dim 5) + zero rows (6,7) of Vt planes — once
        for (int e = tid; e < 3 * 136; e += 256) {
            int d = 5 + e / 136, kk2 = e % 136;
            *reinterpret_cast<unsigned short*>(sm + AVH + (d * 136 + kk2) * 2) =
                (d == 5) ? (unsigned short)0x3F80 : (unsigned short)0;
            *reinterpret_cast<unsigned short*>(sm + AVL + (d * 136 + kk2) * 2) = 0;
        }
        // stage Q (pure copy of packed hi/lo)
        if (tid < 128) {
            uint4 h = *reinterpret_cast<const uint4*>(&g_Qb[bh][qt * 128 + tid][0]);
            uint4 l = *reinterpret_cast<const uint4*>(&g_Qb[bh][qt * 128 + tid][4]);
            *reinterpret_cast<uint4*>(sm + AQH + tid * 16) = h;
            *reinterpret_cast<uint4*>(sm + AQL + tid * 16) = l;
        }
        __syncthreads();

        uint32_t qh0, qh1, ql0, ql1;
        {
            uint32_t w0 = (m0 + r) * 16 + j * 4;
            uint32_t w1 = (m0 + r + 8) * 16 + j * 4;
            qh0 = *reinterpret_cast<const uint32_t*>(sm + AQH + w0);
            qh1 = *reinterpret_cast<const uint32_t*>(sm + AQH + w1);
            ql0 = *reinterpret_cast<const uint32_t*>(sm + AQL + w0);
            ql1 = *reinterpret_cast<const uint32_t*>(sm + AQL + w1);
        }

        for (int ck = t0; ck < t1; ck++) {
            const int key0 = ck * 128;
            __syncthreads();
            if (tid < 128) {
                // V copy: 5 dims x 64 key-pairs x 2 planes = 640 uint32
#pragma unroll
                for (int it = 0; it < 5; it++) {
                    int e = tid + it * 128;
                    int pl = e / 320, rem = e % 320;
                    int d = rem >> 6, kp = rem & 63;
                    uint32_t v = pl
                        ? *reinterpret_cast<const uint32_t*>(&g_Vtl[bh][d][key0 + 2 * kp])
                        : *reinterpret_cast<const uint32_t*>(&g_Vth[bh][d][key0 + 2 * kp]);
                    *reinterpret_cast<uint32_t*>(sm + (pl ? AVL : AVH) + (d * 136 + 2 * kp) * 2) = v;
                }
            } else {
                int key = tid - 128;
                uint4 h = *reinterpret_cast<const uint4*>(&g_Kb[bh][key0 + key][0]);
                uint4 l = *reinterpret_cast<const uint4*>(&g_Kb[bh][key0 + key][4]);
                *reinterpret_cast<uint4*>(sm + AKH + key * 16) = h;
                *reinterpret_cast<uint4*>(sm + AKL + key * 16) = l;
            }
            __syncthreads();

            const bool diag = (ck == qt);

#pragma unroll 2
            for (int ks = 0; ks < 8; ks++) {
                const int kbase = ks * 16;
                if (diag && kbase > m0 + 15) break;
                const bool needMask = diag && (kbase + 15 > m0);

                float c0[4] = {0.f,0.f,0.f,0.f}, c1[4] = {0.f,0.f,0.f,0.f};
                {
                    uint32_t o0 = (kbase + r) * 16 + j * 4;
                    uint32_t o1 = (kbase + 8 + r) * 16 + j * 4;
                    uint32_t b0h = *reinterpret_cast<const uint32_t*>(sm + AKH + o0);
                    uint32_t b0l = *reinterpret_cast<const uint32_t*>(sm + AKL + o0);
                    uint32_t b1h = *reinterpret_cast<const uint32_t*>(sm + AKH + o1);
                    uint32_t b1l = *reinterpret_cast<const uint32_t*>(sm + AKL + o1);
                    mma_k8(c0, qh0, qh1, b0h);
                    mma_k8(c0, qh0, qh1, b0l);
                    mma_k8(c0, ql0, ql1, b0h);
                    mma_k8(c1, qh0, qh1, b1h);
                    mma_k8(c1, qh0, qh1, b1l);
                    mma_k8(c1, ql0, ql1, b1h);
                }

                float p[8];
#pragma unroll
                for (int i = 0; i < 4; i++) p[i]     = ex2_ap(sin_ap(c0[i]) * LOG2E);
#pragma unroll
                for (int i = 0; i < 4; i++) p[4 + i] = ex2_ap(sin_ap(c1[i]) * LOG2E);

                if (needMask) {
                    int q_lo = m0 + r, q_hi = q_lo + 8;
                    int k00 = kbase + 2 * j, k01 = k00 + 1;
                    int k10 = k00 + 8,       k11 = k01 + 8;
                    p[0] = (k00 <= q_lo) ? p[0] : 0.f;
                    p[1] = (k01 <= q_lo) ? p[1] : 0.f;
                    p[2] = (k00 <= q_hi) ? p[2] : 0.f;
                    p[3] = (k01 <= q_hi) ? p[3] : 0.f;
                    p[4] = (k10 <= q_lo) ? p[4] : 0.f;
                    p[5] = (k11 <= q_lo) ? p[5] : 0.f;
                    p[6] = (k10 <= q_hi) ? p[6] : 0.f;
                    p[7] = (k11 <= q_hi) ? p[7] : 0.f;
                }

                uint32_t ah[4], al[4];
#pragma unroll
                for (int i = 0; i < 4; i++) {
                    uint32_t h = pbf2(p[2*i], p[2*i+1]);
                    ah[i] = h;
                    float r0 = __uint_as_float(h << 16);
                    float r1 = __uint_as_float(h & 0xFFFF0000u);
                    al[i] = pbf2(p[2*i] - r0, p[2*i+1] - r1);
                }

                uint32_t vo = (r * 136 + kbase + 2 * j) * 2;
                uint32_t bvh0 = *reinterpret_cast<const uint32_t*>(sm + AVH + vo);
                uint32_t bvh1 = *reinterpret_cast<const uint32_t*>(sm + AVH + vo + 16);
                uint32_t bvl0 = *reinterpret_cast<const uint32_t*>(sm + AVL + vo);
                uint32_t bvl1 = *reinterpret_cast<const uint32_t*>(sm + AVL + vo + 16);

                mma_k16(Cpv, ah, bvh0, bvh1);
                mma_k16(Cpv, ah, bvl0, bvl1);
                mma_k16(Cpv, al, bvh0, bvh1);
            }
        }
    }

    // write partials: cols 0..4 = sum(p*v), col 5 = sum(p); zeros if empty
    if (j < 3) {
        int q1 = qt * 128 + m0 + r;
        *reinterpret_cast<float2*>(&g_A[bh][q1][kz][2 * j]) = make_float2(Cpv[0], Cpv[1]);
        int q2 = q1 + 8;
        *reinterpret_cast<float2*>(&g_A[bh][q2][kz][2 * j]) = make_float2(Cpv[2], Cpv[3]);
    }
}

// =====================================================================
// Kernel 3: combine partials + MLP head on HMMA.
// Block = 128 rows x 512 cols. h1 computed scalar (tiny), staged as
// split-bf16 A [row][40]; Wm2 staged per 128-col chunk as B [n][36];
// out = A@B (3-product split) + bm2, direct float2 stores.
// =====================================================================
#define MA_H 0
#define MA_L (128 * 40 * 2)            // 10240
#define MB_H (2 * 128 * 40 * 2)        // 20480
#define MB_L (MB_H + 128 * 36 * 2)     // 29696
#define MCS  (MB_L + 128 * 36 * 2)     // 38912
#define MBM2 (MCS + 128 * 10 * 4)      // 44032
#define MLP_SM (MBM2 + 512 * 4)        // 46080

__global__ __launch_bounds__(256) void mlp_tc(
    const float* __restrict__ Wm1, const float* __restrict__ bm1,
    const float* __restrict__ Wm2, const float* __restrict__ bm2,
    float* __restrict__ out)
{
    __shared__ __align__(16) char sm[MLP_SM];
    const uint32_t sb = smem_u32(sm);

    const int tid  = threadIdx.x;
    const int wid  = tid >> 5;
    const int lane = tid & 31;
    const int row0 = blockIdx.x * 128;
    const int m0   = wid * 16;

    float* cs   = reinterpret_cast<float*>(sm + MCS);
    float* bm2s = reinterpret_cast<float*>(sm + MBM2);

    // combine attention partials -> c[10] per row
    for (int e = tid; e < 128 * 10; e += 256) {
        int r = e / 10, k = e % 10;
        int h = k / DH, d = k % DH;
        int grow = row0 + r;
        int b = grow >> 11, n = grow & (Nn - 1);
        const float* A = g_A[b * NH + h][n][0];
        float den = 0.f, num = 0.f;
#pragma unroll
        for (int s = 0; s < KZ; s++) {
            num += A[8 * s + d];
            den += A[8 * s + 5];
        }
        cs[e] = num * __fdividef(1.f, den);
    }
    for (int e = tid; e < 512; e += 256) bm2s[e] = bm2[e];
    __syncthreads();

    // zero A k-pad (k 20..31)
    for (int e = tid; e < 128 * 12; e += 256) {
        int r = e / 12, k = 20 + e % 12;
        *reinterpret_cast<unsigned short*>(sm + MA_H + (r * 40 + k) * 2) = 0;
        *reinterpret_cast<unsigned short*>(sm + MA_L + (r * 40 + k) * 2) = 0;
    }
    // h1 = leaky_relu(c @ Wm1 + bm1), split-bf16 into A
    for (int e = tid; e < 128 * HID; e += 256) {
        int r = e / HID, jj = e % HID;
        const float* crow = cs + r * 10;
        float s = bm1[jj];
#pragma unroll
        for (int k = 0; k < DK; k++)
            s = fmaf(crow[k], Wm1[k * HID + jj], s);
        s = (s > 0.f) ? s : 0.01f * s;
        uint32_t bits = __float_as_uint(s);
        *reinterpret_cast<unsigned short*>(sm + MA_H + (r * 40 + jj) * 2) =
            (unsigned short)(bits >> 16);
        *reinterpret_cast<unsigned short*>(sm + MA_L + (r * 40 + jj) * 2) =
            bf16rn(s - __uint_as_float(bits & 0xFFFF0000u));
    }
    __syncthreads();

    // A frags once (2 k16 steps)
    const int arow = lane & 15;
    const int agrp = lane >> 4;
    uint32_t ah[2][4], al[2][4];
#pragma unroll
    for (int ks = 0; ks < 2; ks++) {
        uint32_t abase = (m0 + arow) * 80 + ks * 32 + agrp * 16;
        ldsm4(ah[ks], sb + MA_H + abase);
        ldsm4(al[ks], sb + MA_L + abase);
    }

    const int bn = lane >> 2;
    const int bj = (lane & 3) * 2;
    const int rC = lane >> 2;
    const int jC = lane & 3;

    for (int nc = 0; nc < 4; nc++) {
        __syncthreads();   // prior mma done reading B
        // stage B chunk: [nl][36] u16, k<20 real else 0
        for (int e = tid; e < 128 * 32; e += 256) {
            int k = e >> 7, nl = e & 127;
            float w = (k < HID) ? Wm2[k * DOUT + nc * 128 + nl] : 0.f;
            uint32_t wb = __float_as_uint(w);
            *reinterpret_cast<unsigned short*>(sm + MB_H + (nl * 36 + k) * 2) =
                (unsigned short)(wb >> 16);
            *reinterpret_cast<unsigned short*>(sm + MB_L + (nl * 36 + k) * 2) =
                bf16rn(w - __uint_as_float(wb & 0xFFFF0000u));
        }
        __syncthreads();

#pragma unroll 4
        for (int t = 0; t < 16; t++) {
            float C[4] = {0.f, 0.f, 0.f, 0.f};
#pragma unroll
            for (int ks = 0; ks < 2; ks++) {
                uint32_t bo = ((bn + t * 8) * 36 + ks * 16 + bj) * 2;
                uint32_t bh0 = *reinterpret_cast<const uint32_t*>(sm + MB_H + bo);
                uint32_t bh1 = *reinterpret_cast<const uint32_t*>(sm + MB_H + bo + 16);
                uint32_t bl0 = *reinterpret_cast<const uint32_t*>(sm + MB_L + bo);
                uint32_t bl1 = *reinterpret_cast<const uint32_t*>(sm + MB_L + bo + 16);
                mma_k16(C, ah[ks], bh0, bh1);
                mma_k16(C, ah[ks], bl0, bl1);
                mma_k16(C, al[ks], bh0, bh1);
            }
            int n0 = nc * 128 + t * 8;
            float b0 = bm2s[n0 + 2 * jC], b1 = bm2s[n0 + 2 * jC + 1];
            size_t ro = (size_t)(row0 + m0 + rC) * DOUT + n0 + 2 * jC;
            *reinterpret_cast<float2*>(out + ro) = make_float2(C[0] + b0, C[1] + b1);
            *reinterpret_cast<float2*>(out + ro + 8 * DOUT) = make_float2(C[2] + b0, C[3] + b1);
        }
    }
}

// =====================================================================
extern "C" void kernel_launch(void* const* d_in, const int* in_sizes, int n_in,
                              void* d_out, int out_size)
{
    const float* x   = (const float*)d_in[0];
    const float* Wq  = (const float*)d_in[1];
    const float* bq  = (const float*)d_in[2];
    const float* Wk  = (const float*)d_in[3];
    const float* bk  = (const float*)d_in[4];
    const float* Wv  = (const float*)d_in[5];
    const float* bv  = (const float*)d_in[6];
    const float* Wm1 = (const float*)d_in[7];
    const float* bm1 = (const float*)d_in[8];
    const float* Wm2 = (const float*)d_in[9];
    const float* bm2 = (const float*)d_in[10];

    proj_tc<<<ROWS / 128, 256>>>(x, Wq, bq, Wk, bk, Wv, bv);
    attn_tc<<<dim3(Nn / 128, 32, KZ), 256>>>();
    mlp_tc<<<ROWS / 128, 256>>>(Wm1, bm1, Wm2, bm2, (float*)d_out);
}